// round 9
// baseline (speedup 1.0000x reference)
#include <cuda_runtime.h>
#include <cuda_bf16.h>
#include <math.h>
#include <stdint.h>

#define N_NODES 50000
#define N_EDGES 1600000
#define IN_DIM  1024
#define HID_DIM 2048
#define OUT_DIM 3
#define BN_EPS  1e-5f
#define SCAN_BLOCKS ((N_NODES + 255) / 256)   // 196

// ---------------- scratch ----------------
__device__ int   g_outdeg[N_NODES];
__device__ int   g_indeg[N_NODES];
__device__ float g_outnorm[N_NODES];
__device__ float g_innorm[N_NODES];
__device__ int   g_off[N_NODES + 1];
__device__ int   g_pos[N_NODES];
__device__ int   g_blocksum[SCAN_BLOCKS];
__device__ int   g_col[N_EDGES];
__device__ __nv_bfloat16 g_Ahi[(size_t)N_NODES * IN_DIM];
__device__ __nv_bfloat16 g_Alo[(size_t)N_NODES * IN_DIM];
__device__ __nv_bfloat16 g_Wthi[(size_t)HID_DIM * IN_DIM];
__device__ __nv_bfloat16 g_Wtlo[(size_t)HID_DIM * IN_DIM];
__device__ float g_h[(size_t)N_NODES * HID_DIM];
__device__ float g_bnsum[HID_DIM];
__device__ float g_bnsq[HID_DIM];
__device__ float g_mean[HID_DIM];
__device__ float g_rstd[HID_DIM];
__device__ float g_g[(size_t)N_NODES * OUT_DIM];

// ---------------- PTX helpers (sm_80-compatible only) ----------------
__device__ __forceinline__ uint32_t smem_u32(const void* p) {
    uint32_t a;
    asm("{ .reg .u64 t; cvta.to.shared.u64 t, %1; cvt.u32.u64 %0, t; }" : "=r"(a) : "l"(p));
    return a;
}
__device__ __forceinline__ void cp_async16(uint32_t dst, const void* src, int srcsize) {
    asm volatile("cp.async.cg.shared.global [%0], [%1], 16, %2;\n"
                 :: "r"(dst), "l"(src), "r"(srcsize));
}
#define CP_COMMIT() asm volatile("cp.async.commit_group;\n" ::: "memory")
template<int N> __device__ __forceinline__ void cp_wait() {
    asm volatile("cp.async.wait_group %0;\n" :: "n"(N) : "memory");
}
__device__ __forceinline__ void ldsm4(uint32_t* r, uint32_t addr) {
    asm volatile("ldmatrix.sync.aligned.m8n8.x4.shared.b16 {%0,%1,%2,%3}, [%4];"
                 : "=r"(r[0]), "=r"(r[1]), "=r"(r[2]), "=r"(r[3]) : "r"(addr));
}
__device__ __forceinline__ void mma16816(float* d, const uint32_t* a, uint32_t b0, uint32_t b1) {
    asm volatile(
        "mma.sync.aligned.m16n8k16.row.col.f32.bf16.bf16.f32 "
        "{%0,%1,%2,%3}, {%4,%5,%6,%7}, {%8,%9}, {%0,%1,%2,%3};"
        : "+f"(d[0]), "+f"(d[1]), "+f"(d[2]), "+f"(d[3])
        : "r"(a[0]), "r"(a[1]), "r"(a[2]), "r"(a[3]), "r"(b0), "r"(b1));
}

// ---------------- small kernels ----------------
__global__ void k_zero() {
    int i = blockIdx.x * blockDim.x + threadIdx.x;
    if (i < N_NODES) { g_outdeg[i] = 0; g_indeg[i] = 0; }
    if (i < HID_DIM) { g_bnsum[i] = 0.f; g_bnsq[i] = 0.f; }
}

__global__ void k_deg(const int* __restrict__ src, const int* __restrict__ dst) {
    int e = blockIdx.x * blockDim.x + threadIdx.x;
    if (e < N_EDGES) {
        atomicAdd(&g_outdeg[src[e]], 1);
        atomicAdd(&g_indeg[dst[e]], 1);
    }
}

__global__ void k_norm() {
    int i = blockIdx.x * blockDim.x + threadIdx.x;
    if (i < N_NODES) {
        int od = g_outdeg[i]; if (od < 1) od = 1;
        int id = g_indeg[i];  if (id < 1) id = 1;
        g_outnorm[i] = rsqrtf((float)od);
        g_innorm[i]  = rsqrtf((float)id);
    }
}

// multi-block exclusive scan of g_indeg -> g_off
__global__ void k_scan1() {
    __shared__ int sdata[256];
    int t = threadIdx.x;
    int i = blockIdx.x * 256 + t;
    int x = (i < N_NODES) ? g_indeg[i] : 0;
    sdata[t] = x;
    __syncthreads();
    #pragma unroll
    for (int ofs = 1; ofs < 256; ofs <<= 1) {
        int v = (t >= ofs) ? sdata[t - ofs] : 0;
        __syncthreads();
        sdata[t] += v;
        __syncthreads();
    }
    if (i < N_NODES) g_off[i] = sdata[t] - x;
    if (t == 255) g_blocksum[blockIdx.x] = sdata[255];
}

__global__ void k_scan2() {
    __shared__ int sdata[256];
    int t = threadIdx.x;
    int x = (t < SCAN_BLOCKS) ? g_blocksum[t] : 0;
    sdata[t] = x;
    __syncthreads();
    #pragma unroll
    for (int ofs = 1; ofs < 256; ofs <<= 1) {
        int v = (t >= ofs) ? sdata[t - ofs] : 0;
        __syncthreads();
        sdata[t] += v;
        __syncthreads();
    }
    if (t < SCAN_BLOCKS) g_blocksum[t] = sdata[t] - x;
}

__global__ void k_scan3() {
    int t = threadIdx.x;
    int i = blockIdx.x * 256 + t;
    if (i < N_NODES) {
        int v = g_off[i] + g_blocksum[blockIdx.x];
        g_off[i] = v;
        g_pos[i] = v;
    }
    if (i == 0) g_off[N_NODES] = N_EDGES;
}

__global__ void k_fill(const int* __restrict__ src, const int* __restrict__ dst) {
    int e = blockIdx.x * blockDim.x + threadIdx.x;
    if (e < N_EDGES) {
        int p = atomicAdd(&g_pos[dst[e]], 1);
        g_col[p] = src[e];
    }
}

// split + transpose W1 [K,N] -> Wt_hi/Wt_lo [N,K] bf16
__global__ void k_splitw(const float* __restrict__ W1) {
    int idx = blockIdx.x * blockDim.x + threadIdx.x;
    if (idx < IN_DIM * HID_DIM) {
        int k = idx / HID_DIM, n = idx % HID_DIM;
        float w = W1[idx];
        __nv_bfloat16 hi = __float2bfloat16(w);
        float lo = w - __bfloat162float(hi);
        g_Wthi[(size_t)n * IN_DIM + k] = hi;
        g_Wtlo[(size_t)n * IN_DIM + k] = __float2bfloat16(lo);
    }
}

// SpMM1: agg[row] = in_norm[row] * sum out_norm[s] * X[s]; emit bf16 hi/lo
__global__ void k_spmm1(const float* __restrict__ X) {
    int row = blockIdx.x;
    int t = threadIdx.x;
    int beg = g_off[row], end = g_off[row + 1];
    float ax = 0.f, ay = 0.f, az = 0.f, aw = 0.f;
    int j = beg;
    int s0 = (j < end) ? g_col[j] : 0;
    for (; j < end; j++) {
        int s1 = (j + 1 < end) ? g_col[j + 1] : 0;
        float w = g_outnorm[s0];
        float4 v = *(const float4*)&X[(size_t)s0 * IN_DIM + t * 4];
        ax += w * v.x; ay += w * v.y; az += w * v.z; aw += w * v.w;
        s0 = s1;
    }
    float inw = g_innorm[row];
    float v0 = ax * inw, v1 = ay * inw, v2 = az * inw, v3 = aw * inw;
    __nv_bfloat16 h0 = __float2bfloat16(v0), h1 = __float2bfloat16(v1);
    __nv_bfloat16 h2 = __float2bfloat16(v2), h3 = __float2bfloat16(v3);
    float l0 = v0 - __bfloat162float(h0), l1 = v1 - __bfloat162float(h1);
    float l2 = v2 - __bfloat162float(h2), l3 = v3 - __bfloat162float(h3);
    size_t base = (size_t)row * IN_DIM + t * 4;
    __nv_bfloat162* dh = (__nv_bfloat162*)&g_Ahi[base];
    __nv_bfloat162* dl = (__nv_bfloat162*)&g_Alo[base];
    __nv_bfloat162 p;
    p.x = h0; p.y = h1; dh[0] = p;
    p.x = h2; p.y = h3; dh[1] = p;
    p.x = __float2bfloat16(l0); p.y = __float2bfloat16(l1); dl[0] = p;
    p.x = __float2bfloat16(l2); p.y = __float2bfloat16(l3); dl[1] = p;
}

// ---------------- mma.sync GEMM1, fused-term k-steps ----------------
// BM=128, BN=128, BK=32; stage={Ahi,Alo,Whi,Wlo}=32KB; 3-stage ring; 256 thr, 2 CTA/SM
// 8 warps 4m x 2n; warp tile 32x64; per kstep: hi*hi, lo*hi, hi*lo sharing regs.
// smem rows are 64B (32 bf16); chunk swizzle: c ^ ((r>>1)&3)
#define GBM 128
#define GBN 128
#define STAGE_B 32768          // Ahi 8K @0 | Alo 8K @8K | Whi 8K @16K | Wlo 8K @24K
#define N_KC 32                // 32 k-chunks of 32
#define GDYN (3 * STAGE_B)

__device__ __forceinline__ void g_load_stage(uint32_t sbase, int m0, int n0, int k0, int tid) {
    #pragma unroll
    for (int i = 0; i < 4; i++) {            // Ahi+Alo: 1024 chunks of 16B
        int idx = tid + i * 256;
        int half = idx >> 9;
        int r = (idx & 511) >> 2;
        int c = idx & 3;
        int gm = m0 + r;
        int ok = (gm < N_NODES);
        const __nv_bfloat16* sp = half ? g_Alo : g_Ahi;
        const char* src = (const char*)(sp + (size_t)(ok ? gm : 0) * IN_DIM + k0) + c * 16;
        uint32_t dst = sbase + half * 8192 + r * 64 + ((c ^ ((r >> 1) & 3)) * 16);
        cp_async16(dst, src, ok ? 16 : 0);
    }
    #pragma unroll
    for (int i = 0; i < 4; i++) {            // Whi+Wlo: 1024 chunks of 16B
        int idx = tid + i * 256;
        int half = idx >> 9;
        int r = (idx & 511) >> 2;
        int c = idx & 3;
        const __nv_bfloat16* sp = half ? g_Wtlo : g_Wthi;
        const char* src = (const char*)(sp + (size_t)(n0 + r) * IN_DIM + k0) + c * 16;
        uint32_t dst = sbase + 16384 + half * 8192 + r * 64 + ((c ^ ((r >> 1) & 3)) * 16);
        cp_async16(dst, src, 16);
    }
}

__global__ void __launch_bounds__(256, 2) k_gemm_mma(const float* __restrict__ bias) {
    extern __shared__ char smem[];
    uint32_t sb = smem_u32(smem);
    int tid = threadIdx.x;
    int wid = tid >> 5;
    int lane = tid & 31;
    int n0 = blockIdx.x * GBN;
    int m0 = blockIdx.y * GBM;
    int wm = (wid >> 1) * 32;
    int wn = (wid & 1) * 64;

    float acc[2][8][4];
    #pragma unroll
    for (int i = 0; i < 2; i++)
        #pragma unroll
        for (int j = 0; j < 8; j++)
            #pragma unroll
            for (int q = 0; q < 4; q++) acc[i][j][q] = 0.f;

    g_load_stage(sb + 0 * STAGE_B, m0, n0, 0, tid);
    CP_COMMIT();
    g_load_stage(sb + 1 * STAGE_B, m0, n0, 32, tid);
    CP_COMMIT();

    for (int kc = 0; kc < N_KC; kc++) {
        cp_wait<1>();
        __syncthreads();
        int nx = kc + 2;
        if (nx < N_KC)
            g_load_stage(sb + (nx % 3) * STAGE_B, m0, n0, nx * 32, tid);
        CP_COMMIT();

        uint32_t stg = sb + (kc % 3) * STAGE_B;
        #pragma unroll
        for (int ks = 0; ks < 2; ks++) {
            int ch = ks * 2 + (lane >> 4);    // 0..3
            int ra0 = wm + (lane & 15);
            int ra1 = ra0 + 16;
            uint32_t a_hi[2][4], a_lo[2][4], b[4][4];
            // --- hi * hi ---
            ldsm4(a_hi[0], stg + ra0 * 64 + ((ch ^ ((ra0 >> 1) & 3)) * 16));
            ldsm4(a_hi[1], stg + ra1 * 64 + ((ch ^ ((ra1 >> 1) & 3)) * 16));
            #pragma unroll
            for (int bp = 0; bp < 4; bp++) {
                int r = wn + bp * 16 + (lane & 15);
                ldsm4(b[bp], stg + 16384 + r * 64 + ((ch ^ ((r >> 1) & 3)) * 16));
            }
            #pragma unroll
            for (int am = 0; am < 2; am++)
                #pragma unroll
                for (int bp = 0; bp < 4; bp++) {
                    mma16816(acc[am][bp * 2 + 0], a_hi[am], b[bp][0], b[bp][2]);
                    mma16816(acc[am][bp * 2 + 1], a_hi[am], b[bp][1], b[bp][3]);
                }
            // --- lo * hi (reuse b) ---
            ldsm4(a_lo[0], stg + 8192 + ra0 * 64 + ((ch ^ ((ra0 >> 1) & 3)) * 16));
            ldsm4(a_lo[1], stg + 8192 + ra1 * 64 + ((ch ^ ((ra1 >> 1) & 3)) * 16));
            #pragma unroll
            for (int am = 0; am < 2; am++)
                #pragma unroll
                for (int bp = 0; bp < 4; bp++) {
                    mma16816(acc[am][bp * 2 + 0], a_lo[am], b[bp][0], b[bp][2]);
                    mma16816(acc[am][bp * 2 + 1], a_lo[am], b[bp][1], b[bp][3]);
                }
            // --- hi * lo (reuse a_hi, reload b from Wlo) ---
            #pragma unroll
            for (int bp = 0; bp < 4; bp++) {
                int r = wn + bp * 16 + (lane & 15);
                ldsm4(b[bp], stg + 24576 + r * 64 + ((ch ^ ((r >> 1) & 3)) * 16));
            }
            #pragma unroll
            for (int am = 0; am < 2; am++)
                #pragma unroll
                for (int bp = 0; bp < 4; bp++) {
                    mma16816(acc[am][bp * 2 + 0], a_hi[am], b[bp][0], b[bp][2]);
                    mma16816(acc[am][bp * 2 + 1], a_hi[am], b[bp][1], b[bp][3]);
                }
        }
        __syncthreads();
    }

    // epilogue: +bias, relu, store fp32, fused BN partial sums
    #pragma unroll
    for (int bn8 = 0; bn8 < 8; bn8++) {
        int col = n0 + wn + bn8 * 8 + (lane & 3) * 2;
        float bv0 = __ldg(&bias[col]);
        float bv1 = __ldg(&bias[col + 1]);
        float s0 = 0.f, s1 = 0.f, q0 = 0.f, q1 = 0.f;
        #pragma unroll
        for (int am = 0; am < 2; am++) {
            int row0 = m0 + wm + am * 16 + (lane >> 2);
            if (row0 < N_NODES) {
                float2 o;
                o.x = fmaxf(acc[am][bn8][0] + bv0, 0.f);
                o.y = fmaxf(acc[am][bn8][1] + bv1, 0.f);
                *(float2*)&g_h[(size_t)row0 * HID_DIM + col] = o;
                s0 += o.x; q0 += o.x * o.x;
                s1 += o.y; q1 += o.y * o.y;
            }
            int row1 = row0 + 8;
            if (row1 < N_NODES) {
                float2 o;
                o.x = fmaxf(acc[am][bn8][2] + bv0, 0.f);
                o.y = fmaxf(acc[am][bn8][3] + bv1, 0.f);
                *(float2*)&g_h[(size_t)row1 * HID_DIM + col] = o;
                s0 += o.x; q0 += o.x * o.x;
                s1 += o.y; q1 += o.y * o.y;
            }
        }
        #pragma unroll
        for (int o = 4; o < 32; o <<= 1) {
            s0 += __shfl_xor_sync(0xffffffffu, s0, o);
            s1 += __shfl_xor_sync(0xffffffffu, s1, o);
            q0 += __shfl_xor_sync(0xffffffffu, q0, o);
            q1 += __shfl_xor_sync(0xffffffffu, q1, o);
        }
        if (lane < 4) {
            atomicAdd(&g_bnsum[col], s0);
            atomicAdd(&g_bnsum[col + 1], s1);
            atomicAdd(&g_bnsq[col], q0);
            atomicAdd(&g_bnsq[col + 1], q1);
        }
    }
}

// ---------------- BN finalize ----------------
__global__ void k_bnfin() {
    int c = blockIdx.x * blockDim.x + threadIdx.x;
    if (c < HID_DIM) {
        float m = g_bnsum[c] * (1.f / N_NODES);
        float var = g_bnsq[c] * (1.f / N_NODES) - m * m;
        if (var < 0.f) var = 0.f;
        g_mean[c] = m;
        g_rstd[c] = rsqrtf(var + BN_EPS);
    }
}

// projection: g[i] = (BN(h[i]) * out_norm[i]) @ Wout  (2048 -> 3)
__global__ __launch_bounds__(256) void k_proj(const float* __restrict__ Wout) {
    __shared__ float sW[HID_DIM * OUT_DIM];
    __shared__ float sMean[HID_DIM];
    __shared__ float sRstd[HID_DIM];
    int tid = threadIdx.x;
    for (int i = tid; i < HID_DIM * OUT_DIM; i += 256) sW[i] = Wout[i];
    for (int i = tid; i < HID_DIM; i += 256) { sMean[i] = g_mean[i]; sRstd[i] = g_rstd[i]; }
    __syncthreads();
    int warp = tid >> 5;
    int lane = tid & 31;
    int row = blockIdx.x * 8 + warp;
    if (row >= N_NODES) return;
    const float* hr = &g_h[(size_t)row * HID_DIM];
    float p0 = 0, p1 = 0, p2 = 0;
    for (int c = lane; c < HID_DIM; c += 32) {
        float hn = (hr[c] - sMean[c]) * sRstd[c];
        p0 += hn * sW[c * 3 + 0];
        p1 += hn * sW[c * 3 + 1];
        p2 += hn * sW[c * 3 + 2];
    }
    #pragma unroll
    for (int o = 16; o > 0; o >>= 1) {
        p0 += __shfl_xor_sync(0xffffffffu, p0, o);
        p1 += __shfl_xor_sync(0xffffffffu, p1, o);
        p2 += __shfl_xor_sync(0xffffffffu, p2, o);
    }
    if (lane == 0) {
        float on = g_outnorm[row];
        g_g[row * 3 + 0] = p0 * on;
        g_g[row * 3 + 1] = p1 * on;
        g_g[row * 3 + 2] = p2 * on;
    }
}

// SpMM2 (dim 3) + softmax
__global__ __launch_bounds__(256) void k_spmm2(const float* __restrict__ bout,
                                               float* __restrict__ out) {
    int tid = threadIdx.x;
    int warp = tid >> 5;
    int lane = tid & 31;
    int row = blockIdx.x * 8 + warp;
    if (row >= N_NODES) return;
    int beg = g_off[row], end = g_off[row + 1];
    float a0 = 0, a1 = 0, a2 = 0;
    for (int j = beg + lane; j < end; j += 32) {
        int s = g_col[j];
        a0 += g_g[s * 3 + 0];
        a1 += g_g[s * 3 + 1];
        a2 += g_g[s * 3 + 2];
    }
    #pragma unroll
    for (int o = 16; o > 0; o >>= 1) {
        a0 += __shfl_xor_sync(0xffffffffu, a0, o);
        a1 += __shfl_xor_sync(0xffffffffu, a1, o);
        a2 += __shfl_xor_sync(0xffffffffu, a2, o);
    }
    if (lane == 0) {
        float inw = g_innorm[row];
        float v0 = a0 * inw + bout[0];
        float v1 = a1 * inw + bout[1];
        float v2 = a2 * inw + bout[2];
        float m = fmaxf(v0, fmaxf(v1, v2));
        float e0 = __expf(v0 - m), e1 = __expf(v1 - m), e2 = __expf(v2 - m);
        float inv = 1.f / (e0 + e1 + e2);
        out[row * 3 + 0] = e0 * inv;
        out[row * 3 + 1] = e1 * inv;
        out[row * 3 + 2] = e2 * inv;
    }
}

// ---------------- launch ----------------
extern "C" void kernel_launch(void* const* d_in, const int* in_sizes, int n_in,
                              void* d_out, int out_size) {
    const float* in_feat = (const float*)d_in[0];
    const int*   src     = (const int*)d_in[1];
    const int*   dst     = (const int*)d_in[2];
    const float* W1      = (const float*)d_in[3];
    const float* b1      = (const float*)d_in[4];
    const float* Wout    = (const float*)d_in[5];
    const float* bout    = (const float*)d_in[6];
    float* out = (float*)d_out;

    cudaFuncSetAttribute(k_gemm_mma, cudaFuncAttributeMaxDynamicSharedMemorySize, GDYN);

    k_zero<<<(N_NODES + 255) / 256, 256>>>();
    k_deg<<<(N_EDGES + 255) / 256, 256>>>(src, dst);
    k_norm<<<(N_NODES + 255) / 256, 256>>>();
    k_scan1<<<SCAN_BLOCKS, 256>>>();
    k_scan2<<<1, 256>>>();
    k_scan3<<<SCAN_BLOCKS, 256>>>();
    k_fill<<<(N_EDGES + 255) / 256, 256>>>(src, dst);
    k_splitw<<<(IN_DIM * HID_DIM + 255) / 256, 256>>>(W1);
    k_spmm1<<<N_NODES, 256>>>(in_feat);
    dim3 gg(HID_DIM / GBN, (N_NODES + GBM - 1) / GBM);
    k_gemm_mma<<<gg, 256, GDYN>>>(b1);
    k_bnfin<<<(HID_DIM + 255) / 256, 256>>>();
    k_proj<<<(N_NODES + 7) / 8, 256>>>(Wout);
    k_spmm2<<<(N_NODES + 7) / 8, 256>>>(bout, out);
}

// round 10
// speedup vs baseline: 1.2918x; 1.2918x over previous
#include <cuda_runtime.h>
#include <cuda_fp16.h>
#include <math.h>
#include <stdint.h>

#define N_NODES 50000
#define N_EDGES 1600000
#define IN_DIM  1024
#define HID_DIM 2048
#define OUT_DIM 3
#define BN_EPS  1e-5f
#define SCAN_BLOCKS ((N_NODES + 255) / 256)   // 196

// ---------------- scratch ----------------
__device__ int   g_outdeg[N_NODES];
__device__ int   g_indeg[N_NODES];
__device__ float g_outnorm[N_NODES];
__device__ float g_innorm[N_NODES];
__device__ int   g_off[N_NODES + 1];
__device__ int   g_pos[N_NODES];
__device__ int   g_blocksum[SCAN_BLOCKS];
__device__ int   g_col[N_EDGES];
__device__ __half g_Ah[(size_t)N_NODES * IN_DIM];            // 100 MB  fp16 agg
__device__ __half g_Wthi[(size_t)HID_DIM * IN_DIM];          // 4 MB  [N,K]
__device__ __half g_Wtlo[(size_t)HID_DIM * IN_DIM];          // 4 MB
__device__ float g_h[(size_t)N_NODES * HID_DIM];
__device__ float g_bnsum[HID_DIM];
__device__ float g_bnsq[HID_DIM];
__device__ float g_mean[HID_DIM];
__device__ float g_rstd[HID_DIM];
__device__ float g_g[(size_t)N_NODES * OUT_DIM];

// ---------------- PTX helpers (sm_80-compatible only) ----------------
__device__ __forceinline__ uint32_t smem_u32(const void* p) {
    uint32_t a;
    asm("{ .reg .u64 t; cvta.to.shared.u64 t, %1; cvt.u32.u64 %0, t; }" : "=r"(a) : "l"(p));
    return a;
}
__device__ __forceinline__ void cp_async16(uint32_t dst, const void* src, int srcsize) {
    asm volatile("cp.async.cg.shared.global [%0], [%1], 16, %2;\n"
                 :: "r"(dst), "l"(src), "r"(srcsize));
}
#define CP_COMMIT() asm volatile("cp.async.commit_group;\n" ::: "memory")
template<int N> __device__ __forceinline__ void cp_wait() {
    asm volatile("cp.async.wait_group %0;\n" :: "n"(N) : "memory");
}
__device__ __forceinline__ void ldsm4(uint32_t* r, uint32_t addr) {
    asm volatile("ldmatrix.sync.aligned.m8n8.x4.shared.b16 {%0,%1,%2,%3}, [%4];"
                 : "=r"(r[0]), "=r"(r[1]), "=r"(r[2]), "=r"(r[3]) : "r"(addr));
}
__device__ __forceinline__ void mma16816(float* d, const uint32_t* a, uint32_t b0, uint32_t b1) {
    asm volatile(
        "mma.sync.aligned.m16n8k16.row.col.f32.f16.f16.f32 "
        "{%0,%1,%2,%3}, {%4,%5,%6,%7}, {%8,%9}, {%0,%1,%2,%3};"
        : "+f"(d[0]), "+f"(d[1]), "+f"(d[2]), "+f"(d[3])
        : "r"(a[0]), "r"(a[1]), "r"(a[2]), "r"(a[3]), "r"(b0), "r"(b1));
}

// ---------------- small kernels ----------------
__global__ void k_zero() {
    int i = blockIdx.x * blockDim.x + threadIdx.x;
    if (i < N_NODES) { g_outdeg[i] = 0; g_indeg[i] = 0; }
    if (i < HID_DIM) { g_bnsum[i] = 0.f; g_bnsq[i] = 0.f; }
}

__global__ void k_deg(const int* __restrict__ src, const int* __restrict__ dst) {
    int e = blockIdx.x * blockDim.x + threadIdx.x;
    if (e < N_EDGES) {
        atomicAdd(&g_outdeg[src[e]], 1);
        atomicAdd(&g_indeg[dst[e]], 1);
    }
}

__global__ void k_norm() {
    int i = blockIdx.x * blockDim.x + threadIdx.x;
    if (i < N_NODES) {
        int od = g_outdeg[i]; if (od < 1) od = 1;
        int id = g_indeg[i];  if (id < 1) id = 1;
        g_outnorm[i] = rsqrtf((float)od);
        g_innorm[i]  = rsqrtf((float)id);
    }
}

// multi-block exclusive scan of g_indeg -> g_off
__global__ void k_scan1() {
    __shared__ int sdata[256];
    int t = threadIdx.x;
    int i = blockIdx.x * 256 + t;
    int x = (i < N_NODES) ? g_indeg[i] : 0;
    sdata[t] = x;
    __syncthreads();
    #pragma unroll
    for (int ofs = 1; ofs < 256; ofs <<= 1) {
        int v = (t >= ofs) ? sdata[t - ofs] : 0;
        __syncthreads();
        sdata[t] += v;
        __syncthreads();
    }
    if (i < N_NODES) g_off[i] = sdata[t] - x;
    if (t == 255) g_blocksum[blockIdx.x] = sdata[255];
}

__global__ void k_scan2() {
    __shared__ int sdata[256];
    int t = threadIdx.x;
    int x = (t < SCAN_BLOCKS) ? g_blocksum[t] : 0;
    sdata[t] = x;
    __syncthreads();
    #pragma unroll
    for (int ofs = 1; ofs < 256; ofs <<= 1) {
        int v = (t >= ofs) ? sdata[t - ofs] : 0;
        __syncthreads();
        sdata[t] += v;
        __syncthreads();
    }
    if (t < SCAN_BLOCKS) g_blocksum[t] = sdata[t] - x;
}

__global__ void k_scan3() {
    int t = threadIdx.x;
    int i = blockIdx.x * 256 + t;
    if (i < N_NODES) {
        int v = g_off[i] + g_blocksum[blockIdx.x];
        g_off[i] = v;
        g_pos[i] = v;
    }
    if (i == 0) g_off[N_NODES] = N_EDGES;
}

__global__ void k_fill(const int* __restrict__ src, const int* __restrict__ dst) {
    int e = blockIdx.x * blockDim.x + threadIdx.x;
    if (e < N_EDGES) {
        int p = atomicAdd(&g_pos[dst[e]], 1);
        g_col[p] = src[e];
    }
}

// split + transpose W1 [K,N] -> Wt_hi/Wt_lo [N,K] fp16
__global__ void k_splitw(const float* __restrict__ W1) {
    int idx = blockIdx.x * blockDim.x + threadIdx.x;
    if (idx < IN_DIM * HID_DIM) {
        int k = idx / HID_DIM, n = idx % HID_DIM;
        float w = W1[idx];
        __half hi = __float2half_rn(w);
        float lo = w - __half2float(hi);
        g_Wthi[(size_t)n * IN_DIM + k] = hi;
        g_Wtlo[(size_t)n * IN_DIM + k] = __float2half_rn(lo);
    }
}

// SpMM1: agg[row] = in_norm[row] * sum out_norm[s] * X[s]; emit fp16
__global__ void k_spmm1(const float* __restrict__ X) {
    int row = blockIdx.x;
    int t = threadIdx.x;
    int beg = g_off[row], end = g_off[row + 1];
    float ax = 0.f, ay = 0.f, az = 0.f, aw = 0.f;
    int j = beg;
    int s0 = (j < end) ? g_col[j] : 0;
    for (; j < end; j++) {
        int s1 = (j + 1 < end) ? g_col[j + 1] : 0;
        float w = g_outnorm[s0];
        float4 v = *(const float4*)&X[(size_t)s0 * IN_DIM + t * 4];
        ax += w * v.x; ay += w * v.y; az += w * v.z; aw += w * v.w;
        s0 = s1;
    }
    float inw = g_innorm[row];
    __half2* dh = (__half2*)&g_Ah[(size_t)row * IN_DIM + t * 4];
    dh[0] = __floats2half2_rn(ax * inw, ay * inw);
    dh[1] = __floats2half2_rn(az * inw, aw * inw);
}

// ---------------- mma.sync GEMM1 (round-8 structure, fp16 2-term) ----------------
// BM=128, BN=128, BK=64; 3-stage cp.async pipeline; 8 warps 4m x 2n; warp tile 32x64
#define GBM 128
#define GBN 128
#define STAGE_B 32768           // A 16KB + B 16KB
#define N_ITERS 32              // 2 terms x 16 K-chunks
#define GDYN (3 * STAGE_B)

__device__ __forceinline__ void g_load_stage(uint32_t sbase,
                                             const __half* Ap,
                                             const __half* Bp,
                                             int m0, int n0, int k0, int tid) {
    #pragma unroll
    for (int i = 0; i < 4; i++) {            // A: 128 rows x 64 fp16
        int cid = tid + i * 256;
        int r = cid >> 3, c = cid & 7;
        int gm = m0 + r;
        int ok = (gm < N_NODES);
        const char* src = (const char*)(Ap + (size_t)(ok ? gm : 0) * IN_DIM + k0) + c * 16;
        uint32_t dst = sbase + r * 128 + ((c ^ (r & 7)) * 16);
        cp_async16(dst, src, ok ? 16 : 0);
    }
    #pragma unroll
    for (int i = 0; i < 4; i++) {            // B: 128 n-rows x 64 fp16
        int cid = tid + i * 256;
        int r = cid >> 3, c = cid & 7;
        const char* src = (const char*)(Bp + (size_t)(n0 + r) * IN_DIM + k0) + c * 16;
        uint32_t dst = sbase + 16384 + r * 128 + ((c ^ (r & 7)) * 16);
        cp_async16(dst, src, 16);
    }
}

__global__ void __launch_bounds__(256, 2) k_gemm_mma(const float* __restrict__ bias) {
    extern __shared__ char smem[];
    uint32_t sb = smem_u32(smem);
    int tid = threadIdx.x;
    int wid = tid >> 5;
    int lane = tid & 31;
    int n0 = blockIdx.x * GBN;
    int m0 = blockIdx.y * GBM;
    int wm = (wid >> 1) * 32;
    int wn = (wid & 1) * 64;

    float acc[2][8][4];
    #pragma unroll
    for (int i = 0; i < 2; i++)
        #pragma unroll
        for (int j = 0; j < 8; j++)
            #pragma unroll
            for (int q = 0; q < 4; q++) acc[i][j][q] = 0.f;

    g_load_stage(sb + 0 * STAGE_B, g_Ah, g_Wthi, m0, n0, 0, tid);
    CP_COMMIT();
    g_load_stage(sb + 1 * STAGE_B, g_Ah, g_Wthi, m0, n0, 64, tid);
    CP_COMMIT();

    for (int it = 0; it < N_ITERS; it++) {
        cp_wait<1>();
        __syncthreads();
        int nx = it + 2;
        if (nx < N_ITERS) {
            int term = nx >> 4;
            int kk = (nx & 15) * 64;
            const __half* Bp = (term == 1) ? g_Wtlo : g_Wthi;
            g_load_stage(sb + (nx % 3) * STAGE_B, g_Ah, Bp, m0, n0, kk, tid);
        }
        CP_COMMIT();

        uint32_t bufA = sb + (it % 3) * STAGE_B;
        uint32_t bufB = bufA + 16384;
        #pragma unroll
        for (int ks = 0; ks < 4; ks++) {
            uint32_t a[2][4], b[4][4];
            #pragma unroll
            for (int am = 0; am < 2; am++) {
                int r = wm + am * 16 + (lane & 15);
                int ch = ks * 2 + (lane >> 4);
                ldsm4(a[am], bufA + r * 128 + ((ch ^ (r & 7)) * 16));
            }
            #pragma unroll
            for (int bp = 0; bp < 4; bp++) {
                int r = wn + bp * 16 + (lane & 15);
                int ch = ks * 2 + (lane >> 4);
                ldsm4(b[bp], bufB + r * 128 + ((ch ^ (r & 7)) * 16));
            }
            #pragma unroll
            for (int am = 0; am < 2; am++)
                #pragma unroll
                for (int bp = 0; bp < 4; bp++) {
                    mma16816(acc[am][bp * 2 + 0], a[am], b[bp][0], b[bp][2]);
                    mma16816(acc[am][bp * 2 + 1], a[am], b[bp][1], b[bp][3]);
                }
        }
        __syncthreads();
    }

    // epilogue: +bias, relu, store fp32, fused BN partial sums
    #pragma unroll
    for (int bn8 = 0; bn8 < 8; bn8++) {
        int col = n0 + wn + bn8 * 8 + (lane & 3) * 2;
        float bv0 = __ldg(&bias[col]);
        float bv1 = __ldg(&bias[col + 1]);
        float s0 = 0.f, s1 = 0.f, q0 = 0.f, q1 = 0.f;
        #pragma unroll
        for (int am = 0; am < 2; am++) {
            int row0 = m0 + wm + am * 16 + (lane >> 2);
            if (row0 < N_NODES) {
                float2 o;
                o.x = fmaxf(acc[am][bn8][0] + bv0, 0.f);
                o.y = fmaxf(acc[am][bn8][1] + bv1, 0.f);
                *(float2*)&g_h[(size_t)row0 * HID_DIM + col] = o;
                s0 += o.x; q0 += o.x * o.x;
                s1 += o.y; q1 += o.y * o.y;
            }
            int row1 = row0 + 8;
            if (row1 < N_NODES) {
                float2 o;
                o.x = fmaxf(acc[am][bn8][2] + bv0, 0.f);
                o.y = fmaxf(acc[am][bn8][3] + bv1, 0.f);
                *(float2*)&g_h[(size_t)row1 * HID_DIM + col] = o;
                s0 += o.x; q0 += o.x * o.x;
                s1 += o.y; q1 += o.y * o.y;
            }
        }
        #pragma unroll
        for (int o = 4; o < 32; o <<= 1) {
            s0 += __shfl_xor_sync(0xffffffffu, s0, o);
            s1 += __shfl_xor_sync(0xffffffffu, s1, o);
            q0 += __shfl_xor_sync(0xffffffffu, q0, o);
            q1 += __shfl_xor_sync(0xffffffffu, q1, o);
        }
        if (lane < 4) {
            atomicAdd(&g_bnsum[col], s0);
            atomicAdd(&g_bnsum[col + 1], s1);
            atomicAdd(&g_bnsq[col], q0);
            atomicAdd(&g_bnsq[col + 1], q1);
        }
    }
}

// ---------------- BN finalize ----------------
__global__ void k_bnfin() {
    int c = blockIdx.x * blockDim.x + threadIdx.x;
    if (c < HID_DIM) {
        float m = g_bnsum[c] * (1.f / N_NODES);
        float var = g_bnsq[c] * (1.f / N_NODES) - m * m;
        if (var < 0.f) var = 0.f;
        g_mean[c] = m;
        g_rstd[c] = rsqrtf(var + BN_EPS);
    }
}

// projection: g[i] = (BN(h[i]) * out_norm[i]) @ Wout  (2048 -> 3)
__global__ __launch_bounds__(256) void k_proj(const float* __restrict__ Wout) {
    __shared__ float sW[HID_DIM * OUT_DIM];
    __shared__ float sMean[HID_DIM];
    __shared__ float sRstd[HID_DIM];
    int tid = threadIdx.x;
    for (int i = tid; i < HID_DIM * OUT_DIM; i += 256) sW[i] = Wout[i];
    for (int i = tid; i < HID_DIM; i += 256) { sMean[i] = g_mean[i]; sRstd[i] = g_rstd[i]; }
    __syncthreads();
    int warp = tid >> 5;
    int lane = tid & 31;
    int row = blockIdx.x * 8 + warp;
    if (row >= N_NODES) return;
    const float* hr = &g_h[(size_t)row * HID_DIM];
    float p0 = 0, p1 = 0, p2 = 0;
    for (int c = lane; c < HID_DIM; c += 32) {
        float hn = (hr[c] - sMean[c]) * sRstd[c];
        p0 += hn * sW[c * 3 + 0];
        p1 += hn * sW[c * 3 + 1];
        p2 += hn * sW[c * 3 + 2];
    }
    #pragma unroll
    for (int o = 16; o > 0; o >>= 1) {
        p0 += __shfl_xor_sync(0xffffffffu, p0, o);
        p1 += __shfl_xor_sync(0xffffffffu, p1, o);
        p2 += __shfl_xor_sync(0xffffffffu, p2, o);
    }
    if (lane == 0) {
        float on = g_outnorm[row];
        g_g[row * 3 + 0] = p0 * on;
        g_g[row * 3 + 1] = p1 * on;
        g_g[row * 3 + 2] = p2 * on;
    }
}

// SpMM2 (dim 3) + softmax
__global__ __launch_bounds__(256) void k_spmm2(const float* __restrict__ bout,
                                               float* __restrict__ out) {
    int tid = threadIdx.x;
    int warp = tid >> 5;
    int lane = tid & 31;
    int row = blockIdx.x * 8 + warp;
    if (row >= N_NODES) return;
    int beg = g_off[row], end = g_off[row + 1];
    float a0 = 0, a1 = 0, a2 = 0;
    for (int j = beg + lane; j < end; j += 32) {
        int s = g_col[j];
        a0 += g_g[s * 3 + 0];
        a1 += g_g[s * 3 + 1];
        a2 += g_g[s * 3 + 2];
    }
    #pragma unroll
    for (int o = 16; o > 0; o >>= 1) {
        a0 += __shfl_xor_sync(0xffffffffu, a0, o);
        a1 += __shfl_xor_sync(0xffffffffu, a1, o);
        a2 += __shfl_xor_sync(0xffffffffu, a2, o);
    }
    if (lane == 0) {
        float inw = g_innorm[row];
        float v0 = a0 * inw + bout[0];
        float v1 = a1 * inw + bout[1];
        float v2 = a2 * inw + bout[2];
        float m = fmaxf(v0, fmaxf(v1, v2));
        float e0 = __expf(v0 - m), e1 = __expf(v1 - m), e2 = __expf(v2 - m);
        float inv = 1.f / (e0 + e1 + e2);
        out[row * 3 + 0] = e0 * inv;
        out[row * 3 + 1] = e1 * inv;
        out[row * 3 + 2] = e2 * inv;
    }
}

// ---------------- launch ----------------
extern "C" void kernel_launch(void* const* d_in, const int* in_sizes, int n_in,
                              void* d_out, int out_size) {
    const float* in_feat = (const float*)d_in[0];
    const int*   src     = (const int*)d_in[1];
    const int*   dst     = (const int*)d_in[2];
    const float* W1      = (const float*)d_in[3];
    const float* b1      = (const float*)d_in[4];
    const float* Wout    = (const float*)d_in[5];
    const float* bout    = (const float*)d_in[6];
    float* out = (float*)d_out;

    cudaFuncSetAttribute(k_gemm_mma, cudaFuncAttributeMaxDynamicSharedMemorySize, GDYN);

    k_zero<<<(N_NODES + 255) / 256, 256>>>();
    k_deg<<<(N_EDGES + 255) / 256, 256>>>(src, dst);
    k_norm<<<(N_NODES + 255) / 256, 256>>>();
    k_scan1<<<SCAN_BLOCKS, 256>>>();
    k_scan2<<<1, 256>>>();
    k_scan3<<<SCAN_BLOCKS, 256>>>();
    k_fill<<<(N_EDGES + 255) / 256, 256>>>(src, dst);
    k_splitw<<<(IN_DIM * HID_DIM + 255) / 256, 256>>>(W1);
    k_spmm1<<<N_NODES, 256>>>(in_feat);
    dim3 gg(HID_DIM / GBN, (N_NODES + GBM - 1) / GBM);
    k_gemm_mma<<<gg, 256, GDYN>>>(b1);
    k_bnfin<<<(HID_DIM + 255) / 256, 256>>>();
    k_proj<<<(N_NODES + 7) / 8, 256>>>(Wout);
    k_spmm2<<<(N_NODES + 7) / 8, 256>>>(bout, out);
}

// round 11
// speedup vs baseline: 2.4070x; 1.8632x over previous
#include <cuda_runtime.h>
#include <cuda_fp16.h>
#include <math.h>
#include <stdint.h>

#define N_NODES 50000
#define N_EDGES 1600000
#define IN_DIM  1024
#define HID_DIM 2048
#define OUT_DIM 3
#define BN_EPS  1e-5f
#define SCAN_BLOCKS ((N_NODES + 255) / 256)   // 196

// ---------------- scratch ----------------
__device__ int   g_outdeg[N_NODES];
__device__ int   g_indeg[N_NODES];
__device__ float g_outnorm[N_NODES];
__device__ float g_innorm[N_NODES];
__device__ int   g_off[N_NODES + 1];
__device__ int   g_pos[N_NODES];
__device__ int   g_blocksum[SCAN_BLOCKS];
__device__ int   g_col[N_EDGES];
__device__ __half g_Xh[(size_t)N_NODES * IN_DIM];   // 100 MB: fp16(out_norm * X)
__device__ __half g_Ah[(size_t)N_NODES * IN_DIM];   // 100 MB: fp16 aggregated A
__device__ __half g_Wt[(size_t)HID_DIM * IN_DIM];   // 4 MB  [N,K] fp16 W1^T
__device__ float g_h[(size_t)N_NODES * HID_DIM];
__device__ float g_bnsum[HID_DIM];
__device__ float g_bnsq[HID_DIM];
__device__ float g_mean[HID_DIM];
__device__ float g_rstd[HID_DIM];
__device__ float g_g[(size_t)N_NODES * OUT_DIM];

// ---------------- PTX helpers (sm_80-compatible only) ----------------
__device__ __forceinline__ uint32_t smem_u32(const void* p) {
    uint32_t a;
    asm("{ .reg .u64 t; cvta.to.shared.u64 t, %1; cvt.u32.u64 %0, t; }" : "=r"(a) : "l"(p));
    return a;
}
__device__ __forceinline__ void cp_async16(uint32_t dst, const void* src, int srcsize) {
    asm volatile("cp.async.cg.shared.global [%0], [%1], 16, %2;\n"
                 :: "r"(dst), "l"(src), "r"(srcsize));
}
#define CP_COMMIT() asm volatile("cp.async.commit_group;\n" ::: "memory")
template<int N> __device__ __forceinline__ void cp_wait() {
    asm volatile("cp.async.wait_group %0;\n" :: "n"(N) : "memory");
}
__device__ __forceinline__ void ldsm4(uint32_t* r, uint32_t addr) {
    asm volatile("ldmatrix.sync.aligned.m8n8.x4.shared.b16 {%0,%1,%2,%3}, [%4];"
                 : "=r"(r[0]), "=r"(r[1]), "=r"(r[2]), "=r"(r[3]) : "r"(addr));
}
__device__ __forceinline__ void mma16816(float* d, const uint32_t* a, uint32_t b0, uint32_t b1) {
    asm volatile(
        "mma.sync.aligned.m16n8k16.row.col.f32.f16.f16.f32 "
        "{%0,%1,%2,%3}, {%4,%5,%6,%7}, {%8,%9}, {%0,%1,%2,%3};"
        : "+f"(d[0]), "+f"(d[1]), "+f"(d[2]), "+f"(d[3])
        : "r"(a[0]), "r"(a[1]), "r"(a[2]), "r"(a[3]), "r"(b0), "r"(b1));
}

// ---------------- small kernels ----------------
__global__ void k_zero() {
    int i = blockIdx.x * blockDim.x + threadIdx.x;
    if (i < N_NODES) { g_outdeg[i] = 0; g_indeg[i] = 0; }
    if (i < HID_DIM) { g_bnsum[i] = 0.f; g_bnsq[i] = 0.f; }
}

__global__ void k_deg(const int* __restrict__ src, const int* __restrict__ dst) {
    int e = blockIdx.x * blockDim.x + threadIdx.x;
    if (e < N_EDGES) {
        atomicAdd(&g_outdeg[src[e]], 1);
        atomicAdd(&g_indeg[dst[e]], 1);
    }
}

__global__ void k_norm() {
    int i = blockIdx.x * blockDim.x + threadIdx.x;
    if (i < N_NODES) {
        int od = g_outdeg[i]; if (od < 1) od = 1;
        int id = g_indeg[i];  if (id < 1) id = 1;
        g_outnorm[i] = rsqrtf((float)od);
        g_innorm[i]  = rsqrtf((float)id);
    }
}

// multi-block exclusive scan of g_indeg -> g_off
__global__ void k_scan1() {
    __shared__ int sdata[256];
    int t = threadIdx.x;
    int i = blockIdx.x * 256 + t;
    int x = (i < N_NODES) ? g_indeg[i] : 0;
    sdata[t] = x;
    __syncthreads();
    #pragma unroll
    for (int ofs = 1; ofs < 256; ofs <<= 1) {
        int v = (t >= ofs) ? sdata[t - ofs] : 0;
        __syncthreads();
        sdata[t] += v;
        __syncthreads();
    }
    if (i < N_NODES) g_off[i] = sdata[t] - x;
    if (t == 255) g_blocksum[blockIdx.x] = sdata[255];
}

__global__ void k_scan2() {
    __shared__ int sdata[256];
    int t = threadIdx.x;
    int x = (t < SCAN_BLOCKS) ? g_blocksum[t] : 0;
    sdata[t] = x;
    __syncthreads();
    #pragma unroll
    for (int ofs = 1; ofs < 256; ofs <<= 1) {
        int v = (t >= ofs) ? sdata[t - ofs] : 0;
        __syncthreads();
        sdata[t] += v;
        __syncthreads();
    }
    if (t < SCAN_BLOCKS) g_blocksum[t] = sdata[t] - x;
}

__global__ void k_scan3() {
    int t = threadIdx.x;
    int i = blockIdx.x * 256 + t;
    if (i < N_NODES) {
        int v = g_off[i] + g_blocksum[blockIdx.x];
        g_off[i] = v;
        g_pos[i] = v;
    }
    if (i == 0) g_off[N_NODES] = N_EDGES;
}

__global__ void k_fill(const int* __restrict__ src, const int* __restrict__ dst) {
    int e = blockIdx.x * blockDim.x + threadIdx.x;
    if (e < N_EDGES) {
        int p = atomicAdd(&g_pos[dst[e]], 1);
        g_col[p] = src[e];
    }
}

// transpose W1 [K,N] -> Wt [N,K] fp16
__global__ void k_transw(const float* __restrict__ W1) {
    int idx = blockIdx.x * blockDim.x + threadIdx.x;
    if (idx < IN_DIM * HID_DIM) {
        int k = idx / HID_DIM, n = idx % HID_DIM;
        g_Wt[(size_t)n * IN_DIM + k] = __float2half_rn(W1[idx]);
    }
}

// pre-scale + quantize: Xh[i] = fp16(out_norm[i] * X[i])
__global__ void k_prep(const float* __restrict__ X) {
    int idx = blockIdx.x * blockDim.x + threadIdx.x;   // one float4 / thread
    if (idx < N_NODES * (IN_DIM / 4)) {
        int row = idx >> 8;                            // IN_DIM/4 = 256
        float w = g_outnorm[row];
        float4 v = *(const float4*)&X[(size_t)idx * 4];
        __half2* d = (__half2*)&g_Xh[(size_t)idx * 4];
        d[0] = __floats2half2_rn(v.x * w, v.y * w);
        d[1] = __floats2half2_rn(v.z * w, v.w * w);
    }
}

// SpMM1: Ah[row] = fp16( in_norm[row] * sum Xh[s] );  fp16 gather (2KB rows)
__global__ void k_spmm1() {
    int row = blockIdx.x;
    int t = threadIdx.x;
    int beg = g_off[row], end = g_off[row + 1];
    float a0 = 0.f, a1 = 0.f, a2 = 0.f, a3 = 0.f;
    for (int j = beg; j < end; j++) {
        int s = g_col[j];
        uint2 u = *(const uint2*)&g_Xh[(size_t)s * IN_DIM + t * 4];
        float2 f0 = __half22float2(*(__half2*)&u.x);
        float2 f1 = __half22float2(*(__half2*)&u.y);
        a0 += f0.x; a1 += f0.y; a2 += f1.x; a3 += f1.y;
    }
    float inw = g_innorm[row];
    __half2* d = (__half2*)&g_Ah[(size_t)row * IN_DIM + t * 4];
    d[0] = __floats2half2_rn(a0 * inw, a1 * inw);
    d[1] = __floats2half2_rn(a2 * inw, a3 * inw);
}

// ---------------- mma.sync GEMM1, single-term fp16 ----------------
// BM=128, BN=128, BK=64; 3-stage cp.async pipeline; 8 warps 4m x 2n; warp tile 32x64
#define GBM 128
#define GBN 128
#define STAGE_B 32768           // A 16KB + B 16KB
#define N_ITERS 16              // 16 K-chunks of 64
#define GDYN (3 * STAGE_B)

__device__ __forceinline__ void g_load_stage(uint32_t sbase, int m0, int n0, int k0, int tid) {
    #pragma unroll
    for (int i = 0; i < 4; i++) {            // A: 128 rows x 64 fp16
        int cid = tid + i * 256;
        int r = cid >> 3, c = cid & 7;
        int gm = m0 + r;
        int ok = (gm < N_NODES);
        const char* src = (const char*)(g_Ah + (size_t)(ok ? gm : 0) * IN_DIM + k0) + c * 16;
        uint32_t dst = sbase + r * 128 + ((c ^ (r & 7)) * 16);
        cp_async16(dst, src, ok ? 16 : 0);
    }
    #pragma unroll
    for (int i = 0; i < 4; i++) {            // B: 128 n-rows x 64 fp16
        int cid = tid + i * 256;
        int r = cid >> 3, c = cid & 7;
        const char* src = (const char*)(g_Wt + (size_t)(n0 + r) * IN_DIM + k0) + c * 16;
        uint32_t dst = sbase + 16384 + r * 128 + ((c ^ (r & 7)) * 16);
        cp_async16(dst, src, 16);
    }
}

__global__ void __launch_bounds__(256, 2) k_gemm_mma(const float* __restrict__ bias) {
    extern __shared__ char smem[];
    uint32_t sb = smem_u32(smem);
    int tid = threadIdx.x;
    int wid = tid >> 5;
    int lane = tid & 31;
    int n0 = blockIdx.x * GBN;
    int m0 = blockIdx.y * GBM;
    int wm = (wid >> 1) * 32;
    int wn = (wid & 1) * 64;

    float acc[2][8][4];
    #pragma unroll
    for (int i = 0; i < 2; i++)
        #pragma unroll
        for (int j = 0; j < 8; j++)
            #pragma unroll
            for (int q = 0; q < 4; q++) acc[i][j][q] = 0.f;

    g_load_stage(sb + 0 * STAGE_B, m0, n0, 0, tid);
    CP_COMMIT();
    g_load_stage(sb + 1 * STAGE_B, m0, n0, 64, tid);
    CP_COMMIT();

    for (int it = 0; it < N_ITERS; it++) {
        cp_wait<1>();
        __syncthreads();
        int nx = it + 2;
        if (nx < N_ITERS)
            g_load_stage(sb + (nx % 3) * STAGE_B, m0, n0, nx * 64, tid);
        CP_COMMIT();

        uint32_t bufA = sb + (it % 3) * STAGE_B;
        uint32_t bufB = bufA + 16384;
        #pragma unroll
        for (int ks = 0; ks < 4; ks++) {
            uint32_t a[2][4], b[4][4];
            #pragma unroll
            for (int am = 0; am < 2; am++) {
                int r = wm + am * 16 + (lane & 15);
                int ch = ks * 2 + (lane >> 4);
                ldsm4(a[am], bufA + r * 128 + ((ch ^ (r & 7)) * 16));
            }
            #pragma unroll
            for (int bp = 0; bp < 4; bp++) {
                int r = wn + bp * 16 + (lane & 15);
                int ch = ks * 2 + (lane >> 4);
                ldsm4(b[bp], bufB + r * 128 + ((ch ^ (r & 7)) * 16));
            }
            #pragma unroll
            for (int am = 0; am < 2; am++)
                #pragma unroll
                for (int bp = 0; bp < 4; bp++) {
                    mma16816(acc[am][bp * 2 + 0], a[am], b[bp][0], b[bp][2]);
                    mma16816(acc[am][bp * 2 + 1], a[am], b[bp][1], b[bp][3]);
                }
        }
        __syncthreads();
    }

    // epilogue: +bias, relu, store fp32, fused BN partial sums
    #pragma unroll
    for (int bn8 = 0; bn8 < 8; bn8++) {
        int col = n0 + wn + bn8 * 8 + (lane & 3) * 2;
        float bv0 = __ldg(&bias[col]);
        float bv1 = __ldg(&bias[col + 1]);
        float s0 = 0.f, s1 = 0.f, q0 = 0.f, q1 = 0.f;
        #pragma unroll
        for (int am = 0; am < 2; am++) {
            int row0 = m0 + wm + am * 16 + (lane >> 2);
            if (row0 < N_NODES) {
                float2 o;
                o.x = fmaxf(acc[am][bn8][0] + bv0, 0.f);
                o.y = fmaxf(acc[am][bn8][1] + bv1, 0.f);
                *(float2*)&g_h[(size_t)row0 * HID_DIM + col] = o;
                s0 += o.x; q0 += o.x * o.x;
                s1 += o.y; q1 += o.y * o.y;
            }
            int row1 = row0 + 8;
            if (row1 < N_NODES) {
                float2 o;
                o.x = fmaxf(acc[am][bn8][2] + bv0, 0.f);
                o.y = fmaxf(acc[am][bn8][3] + bv1, 0.f);
                *(float2*)&g_h[(size_t)row1 * HID_DIM + col] = o;
                s0 += o.x; q0 += o.x * o.x;
                s1 += o.y; q1 += o.y * o.y;
            }
        }
        #pragma unroll
        for (int o = 4; o < 32; o <<= 1) {
            s0 += __shfl_xor_sync(0xffffffffu, s0, o);
            s1 += __shfl_xor_sync(0xffffffffu, s1, o);
            q0 += __shfl_xor_sync(0xffffffffu, q0, o);
            q1 += __shfl_xor_sync(0xffffffffu, q1, o);
        }
        if (lane < 4) {
            atomicAdd(&g_bnsum[col], s0);
            atomicAdd(&g_bnsum[col + 1], s1);
            atomicAdd(&g_bnsq[col], q0);
            atomicAdd(&g_bnsq[col + 1], q1);
        }
    }
}

// ---------------- BN finalize ----------------
__global__ void k_bnfin() {
    int c = blockIdx.x * blockDim.x + threadIdx.x;
    if (c < HID_DIM) {
        float m = g_bnsum[c] * (1.f / N_NODES);
        float var = g_bnsq[c] * (1.f / N_NODES) - m * m;
        if (var < 0.f) var = 0.f;
        g_mean[c] = m;
        g_rstd[c] = rsqrtf(var + BN_EPS);
    }
}

// projection: g[i] = (BN(h[i]) * out_norm[i]) @ Wout  (2048 -> 3)
__global__ __launch_bounds__(256) void k_proj(const float* __restrict__ Wout) {
    __shared__ float sW[HID_DIM * OUT_DIM];
    __shared__ float sMean[HID_DIM];
    __shared__ float sRstd[HID_DIM];
    int tid = threadIdx.x;
    for (int i = tid; i < HID_DIM * OUT_DIM; i += 256) sW[i] = Wout[i];
    for (int i = tid; i < HID_DIM; i += 256) { sMean[i] = g_mean[i]; sRstd[i] = g_rstd[i]; }
    __syncthreads();
    int warp = tid >> 5;
    int lane = tid & 31;
    int row = blockIdx.x * 8 + warp;
    if (row >= N_NODES) return;
    const float* hr = &g_h[(size_t)row * HID_DIM];
    float p0 = 0, p1 = 0, p2 = 0;
    for (int c = lane; c < HID_DIM; c += 32) {
        float hn = (hr[c] - sMean[c]) * sRstd[c];
        p0 += hn * sW[c * 3 + 0];
        p1 += hn * sW[c * 3 + 1];
        p2 += hn * sW[c * 3 + 2];
    }
    #pragma unroll
    for (int o = 16; o > 0; o >>= 1) {
        p0 += __shfl_xor_sync(0xffffffffu, p0, o);
        p1 += __shfl_xor_sync(0xffffffffu, p1, o);
        p2 += __shfl_xor_sync(0xffffffffu, p2, o);
    }
    if (lane == 0) {
        float on = g_outnorm[row];
        g_g[row * 3 + 0] = p0 * on;
        g_g[row * 3 + 1] = p1 * on;
        g_g[row * 3 + 2] = p2 * on;
    }
}

// SpMM2 (dim 3) + softmax
__global__ __launch_bounds__(256) void k_spmm2(const float* __restrict__ bout,
                                               float* __restrict__ out) {
    int tid = threadIdx.x;
    int warp = tid >> 5;
    int lane = tid & 31;
    int row = blockIdx.x * 8 + warp;
    if (row >= N_NODES) return;
    int beg = g_off[row], end = g_off[row + 1];
    float a0 = 0, a1 = 0, a2 = 0;
    for (int j = beg + lane; j < end; j += 32) {
        int s = g_col[j];
        a0 += g_g[s * 3 + 0];
        a1 += g_g[s * 3 + 1];
        a2 += g_g[s * 3 + 2];
    }
    #pragma unroll
    for (int o = 16; o > 0; o >>= 1) {
        a0 += __shfl_xor_sync(0xffffffffu, a0, o);
        a1 += __shfl_xor_sync(0xffffffffu, a1, o);
        a2 += __shfl_xor_sync(0xffffffffu, a2, o);
    }
    if (lane == 0) {
        float inw = g_innorm[row];
        float v0 = a0 * inw + bout[0];
        float v1 = a1 * inw + bout[1];
        float v2 = a2 * inw + bout[2];
        float m = fmaxf(v0, fmaxf(v1, v2));
        float e0 = __expf(v0 - m), e1 = __expf(v1 - m), e2 = __expf(v2 - m);
        float inv = 1.f / (e0 + e1 + e2);
        out[row * 3 + 0] = e0 * inv;
        out[row * 3 + 1] = e1 * inv;
        out[row * 3 + 2] = e2 * inv;
    }
}

// ---------------- launch ----------------
extern "C" void kernel_launch(void* const* d_in, const int* in_sizes, int n_in,
                              void* d_out, int out_size) {
    const float* in_feat = (const float*)d_in[0];
    const int*   src     = (const int*)d_in[1];
    const int*   dst     = (const int*)d_in[2];
    const float* W1      = (const float*)d_in[3];
    const float* b1      = (const float*)d_in[4];
    const float* Wout    = (const float*)d_in[5];
    const float* bout    = (const float*)d_in[6];
    float* out = (float*)d_out;

    cudaFuncSetAttribute(k_gemm_mma, cudaFuncAttributeMaxDynamicSharedMemorySize, GDYN);

    k_zero<<<(N_NODES + 255) / 256, 256>>>();
    k_deg<<<(N_EDGES + 255) / 256, 256>>>(src, dst);
    k_norm<<<(N_NODES + 255) / 256, 256>>>();
    k_scan1<<<SCAN_BLOCKS, 256>>>();
    k_scan2<<<1, 256>>>();
    k_scan3<<<SCAN_BLOCKS, 256>>>();
    k_fill<<<(N_EDGES + 255) / 256, 256>>>(src, dst);
    k_transw<<<(IN_DIM * HID_DIM + 255) / 256, 256>>>(W1);
    k_prep<<<(N_NODES * (IN_DIM / 4) + 255) / 256, 256>>>(in_feat);
    k_spmm1<<<N_NODES, 256>>>();
    dim3 gg(HID_DIM / GBN, (N_NODES + GBM - 1) / GBM);
    k_gemm_mma<<<gg, 256, GDYN>>>(b1);
    k_bnfin<<<(HID_DIM + 255) / 256, 256>>>();
    k_proj<<<(N_NODES + 7) / 8, 256>>>(Wout);
    k_spmm2<<<(N_NODES + 7) / 8, 256>>>(bout, out);
}

// round 12
// speedup vs baseline: 2.4725x; 1.0272x over previous
#include <cuda_runtime.h>
#include <cuda_fp16.h>
#include <math.h>
#include <stdint.h>

#define N_NODES 50000
#define N_EDGES 1600000
#define IN_DIM  1024
#define HID_DIM 2048
#define OUT_DIM 3
#define BN_EPS  1e-5f
#define SCAN_BLOCKS ((N_NODES + 255) / 256)   // 196

// ---------------- scratch ----------------
__device__ int   g_outdeg[N_NODES];
__device__ int   g_indeg[N_NODES];
__device__ float g_outnorm[N_NODES];
__device__ float g_innorm[N_NODES];
__device__ int   g_off[N_NODES + 1];
__device__ int   g_pos[N_NODES];
__device__ int   g_blocksum[SCAN_BLOCKS];
__device__ int   g_col[N_EDGES];
__device__ __half g_Xh[(size_t)N_NODES * IN_DIM];   // 100 MB: fp16(out_norm * X)
__device__ __half g_Ah[(size_t)N_NODES * IN_DIM];   // 100 MB: fp16 aggregated A
__device__ __half g_Wt[(size_t)HID_DIM * IN_DIM];   // 4 MB  [N,K] fp16 W1^T
__device__ __half g_hh[(size_t)N_NODES * HID_DIM];  // 205 MB fp16 relu(h)
__device__ float g_bnsum[HID_DIM];
__device__ float g_bnsq[HID_DIM];
__device__ float g_mean[HID_DIM];
__device__ float g_rstd[HID_DIM];
__device__ float g_g[(size_t)N_NODES * OUT_DIM];

// ---------------- PTX helpers (sm_80-compatible only) ----------------
__device__ __forceinline__ uint32_t smem_u32(const void* p) {
    uint32_t a;
    asm("{ .reg .u64 t; cvta.to.shared.u64 t, %1; cvt.u32.u64 %0, t; }" : "=r"(a) : "l"(p));
    return a;
}
__device__ __forceinline__ void cp_async16(uint32_t dst, const void* src, int srcsize) {
    asm volatile("cp.async.cg.shared.global [%0], [%1], 16, %2;\n"
                 :: "r"(dst), "l"(src), "r"(srcsize));
}
#define CP_COMMIT() asm volatile("cp.async.commit_group;\n" ::: "memory")
template<int N> __device__ __forceinline__ void cp_wait() {
    asm volatile("cp.async.wait_group %0;\n" :: "n"(N) : "memory");
}
__device__ __forceinline__ void ldsm4(uint32_t* r, uint32_t addr) {
    asm volatile("ldmatrix.sync.aligned.m8n8.x4.shared.b16 {%0,%1,%2,%3}, [%4];"
                 : "=r"(r[0]), "=r"(r[1]), "=r"(r[2]), "=r"(r[3]) : "r"(addr));
}
__device__ __forceinline__ void mma16816(float* d, const uint32_t* a, uint32_t b0, uint32_t b1) {
    asm volatile(
        "mma.sync.aligned.m16n8k16.row.col.f32.f16.f16.f32 "
        "{%0,%1,%2,%3}, {%4,%5,%6,%7}, {%8,%9}, {%0,%1,%2,%3};"
        : "+f"(d[0]), "+f"(d[1]), "+f"(d[2]), "+f"(d[3])
        : "r"(a[0]), "r"(a[1]), "r"(a[2]), "r"(a[3]), "r"(b0), "r"(b1));
}

// ---------------- small kernels ----------------
__global__ void k_zero() {
    int i = blockIdx.x * blockDim.x + threadIdx.x;
    if (i < N_NODES) { g_outdeg[i] = 0; g_indeg[i] = 0; }
    if (i < HID_DIM) { g_bnsum[i] = 0.f; g_bnsq[i] = 0.f; }
}

__global__ void k_deg(const int* __restrict__ src, const int* __restrict__ dst) {
    int e = blockIdx.x * blockDim.x + threadIdx.x;
    if (e < N_EDGES) {
        atomicAdd(&g_outdeg[src[e]], 1);
        atomicAdd(&g_indeg[dst[e]], 1);
    }
}

__global__ void k_norm() {
    int i = blockIdx.x * blockDim.x + threadIdx.x;
    if (i < N_NODES) {
        int od = g_outdeg[i]; if (od < 1) od = 1;
        int id = g_indeg[i];  if (id < 1) id = 1;
        g_outnorm[i] = rsqrtf((float)od);
        g_innorm[i]  = rsqrtf((float)id);
    }
}

// multi-block exclusive scan of g_indeg -> g_off
__global__ void k_scan1() {
    __shared__ int sdata[256];
    int t = threadIdx.x;
    int i = blockIdx.x * 256 + t;
    int x = (i < N_NODES) ? g_indeg[i] : 0;
    sdata[t] = x;
    __syncthreads();
    #pragma unroll
    for (int ofs = 1; ofs < 256; ofs <<= 1) {
        int v = (t >= ofs) ? sdata[t - ofs] : 0;
        __syncthreads();
        sdata[t] += v;
        __syncthreads();
    }
    if (i < N_NODES) g_off[i] = sdata[t] - x;
    if (t == 255) g_blocksum[blockIdx.x] = sdata[255];
}

__global__ void k_scan2() {
    __shared__ int sdata[256];
    int t = threadIdx.x;
    int x = (t < SCAN_BLOCKS) ? g_blocksum[t] : 0;
    sdata[t] = x;
    __syncthreads();
    #pragma unroll
    for (int ofs = 1; ofs < 256; ofs <<= 1) {
        int v = (t >= ofs) ? sdata[t - ofs] : 0;
        __syncthreads();
        sdata[t] += v;
        __syncthreads();
    }
    if (t < SCAN_BLOCKS) g_blocksum[t] = sdata[t] - x;
}

__global__ void k_scan3() {
    int t = threadIdx.x;
    int i = blockIdx.x * 256 + t;
    if (i < N_NODES) {
        int v = g_off[i] + g_blocksum[blockIdx.x];
        g_off[i] = v;
        g_pos[i] = v;
    }
    if (i == 0) g_off[N_NODES] = N_EDGES;
}

__global__ void k_fill(const int* __restrict__ src, const int* __restrict__ dst) {
    int e = blockIdx.x * blockDim.x + threadIdx.x;
    if (e < N_EDGES) {
        int p = atomicAdd(&g_pos[dst[e]], 1);
        g_col[p] = src[e];
    }
}

// transpose W1 [K,N] -> Wt [N,K] fp16
__global__ void k_transw(const float* __restrict__ W1) {
    int idx = blockIdx.x * blockDim.x + threadIdx.x;
    if (idx < IN_DIM * HID_DIM) {
        int k = idx / HID_DIM, n = idx % HID_DIM;
        g_Wt[(size_t)n * IN_DIM + k] = __float2half_rn(W1[idx]);
    }
}

// pre-scale + quantize: Xh[i] = fp16(out_norm[i] * X[i])
__global__ void k_prep(const float* __restrict__ X) {
    int idx = blockIdx.x * blockDim.x + threadIdx.x;   // one float4 / thread
    if (idx < N_NODES * (IN_DIM / 4)) {
        int row = idx >> 8;                            // IN_DIM/4 = 256
        float w = g_outnorm[row];
        float4 v = *(const float4*)&X[(size_t)idx * 4];
        __half2* d = (__half2*)&g_Xh[(size_t)idx * 4];
        d[0] = __floats2half2_rn(v.x * w, v.y * w);
        d[1] = __floats2half2_rn(v.z * w, v.w * w);
    }
}

// SpMM1: Ah[row] = fp16( in_norm[row] * sum Xh[s] );  fp16 gather (2KB rows)
__global__ void k_spmm1() {
    int row = blockIdx.x;
    int t = threadIdx.x;
    int beg = g_off[row], end = g_off[row + 1];
    float a0 = 0.f, a1 = 0.f, a2 = 0.f, a3 = 0.f;
    for (int j = beg; j < end; j++) {
        int s = g_col[j];
        uint2 u = *(const uint2*)&g_Xh[(size_t)s * IN_DIM + t * 4];
        float2 f0 = __half22float2(*(__half2*)&u.x);
        float2 f1 = __half22float2(*(__half2*)&u.y);
        a0 += f0.x; a1 += f0.y; a2 += f1.x; a3 += f1.y;
    }
    float inw = g_innorm[row];
    __half2* d = (__half2*)&g_Ah[(size_t)row * IN_DIM + t * 4];
    d[0] = __floats2half2_rn(a0 * inw, a1 * inw);
    d[1] = __floats2half2_rn(a2 * inw, a3 * inw);
}

// ---------------- mma.sync GEMM1, single-term fp16 ----------------
// BM=128, BN=128, BK=64; 3-stage cp.async pipeline; 8 warps 4m x 2n; warp tile 32x64
#define GBM 128
#define GBN 128
#define STAGE_B 32768           // A 16KB + B 16KB
#define N_ITERS 16              // 16 K-chunks of 64
#define GDYN (3 * STAGE_B)

__device__ __forceinline__ void g_load_stage(uint32_t sbase, int m0, int n0, int k0, int tid) {
    #pragma unroll
    for (int i = 0; i < 4; i++) {            // A: 128 rows x 64 fp16
        int cid = tid + i * 256;
        int r = cid >> 3, c = cid & 7;
        int gm = m0 + r;
        int ok = (gm < N_NODES);
        const char* src = (const char*)(g_Ah + (size_t)(ok ? gm : 0) * IN_DIM + k0) + c * 16;
        uint32_t dst = sbase + r * 128 + ((c ^ (r & 7)) * 16);
        cp_async16(dst, src, ok ? 16 : 0);
    }
    #pragma unroll
    for (int i = 0; i < 4; i++) {            // B: 128 n-rows x 64 fp16
        int cid = tid + i * 256;
        int r = cid >> 3, c = cid & 7;
        const char* src = (const char*)(g_Wt + (size_t)(n0 + r) * IN_DIM + k0) + c * 16;
        uint32_t dst = sbase + 16384 + r * 128 + ((c ^ (r & 7)) * 16);
        cp_async16(dst, src, 16);
    }
}

__global__ void __launch_bounds__(256, 2) k_gemm_mma(const float* __restrict__ bias) {
    extern __shared__ char smem[];
    uint32_t sb = smem_u32(smem);
    int tid = threadIdx.x;
    int wid = tid >> 5;
    int lane = tid & 31;
    int n0 = blockIdx.x * GBN;
    int m0 = blockIdx.y * GBM;
    int wm = (wid >> 1) * 32;
    int wn = (wid & 1) * 64;

    float acc[2][8][4];
    #pragma unroll
    for (int i = 0; i < 2; i++)
        #pragma unroll
        for (int j = 0; j < 8; j++)
            #pragma unroll
            for (int q = 0; q < 4; q++) acc[i][j][q] = 0.f;

    g_load_stage(sb + 0 * STAGE_B, m0, n0, 0, tid);
    CP_COMMIT();
    g_load_stage(sb + 1 * STAGE_B, m0, n0, 64, tid);
    CP_COMMIT();

    for (int it = 0; it < N_ITERS; it++) {
        cp_wait<1>();
        __syncthreads();
        int nx = it + 2;
        if (nx < N_ITERS)
            g_load_stage(sb + (nx % 3) * STAGE_B, m0, n0, nx * 64, tid);
        CP_COMMIT();

        uint32_t bufA = sb + (it % 3) * STAGE_B;
        uint32_t bufB = bufA + 16384;
        #pragma unroll
        for (int ks = 0; ks < 4; ks++) {
            uint32_t a[2][4], b[4][4];
            #pragma unroll
            for (int am = 0; am < 2; am++) {
                int r = wm + am * 16 + (lane & 15);
                int ch = ks * 2 + (lane >> 4);
                ldsm4(a[am], bufA + r * 128 + ((ch ^ (r & 7)) * 16));
            }
            #pragma unroll
            for (int bp = 0; bp < 4; bp++) {
                int r = wn + bp * 16 + (lane & 15);
                int ch = ks * 2 + (lane >> 4);
                ldsm4(b[bp], bufB + r * 128 + ((ch ^ (r & 7)) * 16));
            }
            #pragma unroll
            for (int am = 0; am < 2; am++)
                #pragma unroll
                for (int bp = 0; bp < 4; bp++) {
                    mma16816(acc[am][bp * 2 + 0], a[am], b[bp][0], b[bp][2]);
                    mma16816(acc[am][bp * 2 + 1], a[am], b[bp][1], b[bp][3]);
                }
        }
        __syncthreads();
    }

    // epilogue: +bias, relu, fp16 store, fused BN partial sums (from fp32 values)
    #pragma unroll
    for (int bn8 = 0; bn8 < 8; bn8++) {
        int col = n0 + wn + bn8 * 8 + (lane & 3) * 2;
        float bv0 = __ldg(&bias[col]);
        float bv1 = __ldg(&bias[col + 1]);
        float s0 = 0.f, s1 = 0.f, q0 = 0.f, q1 = 0.f;
        #pragma unroll
        for (int am = 0; am < 2; am++) {
            int row0 = m0 + wm + am * 16 + (lane >> 2);
            if (row0 < N_NODES) {
                float ox = fmaxf(acc[am][bn8][0] + bv0, 0.f);
                float oy = fmaxf(acc[am][bn8][1] + bv1, 0.f);
                *(__half2*)&g_hh[(size_t)row0 * HID_DIM + col] = __floats2half2_rn(ox, oy);
                s0 += ox; q0 += ox * ox;
                s1 += oy; q1 += oy * oy;
            }
            int row1 = row0 + 8;
            if (row1 < N_NODES) {
                float ox = fmaxf(acc[am][bn8][2] + bv0, 0.f);
                float oy = fmaxf(acc[am][bn8][3] + bv1, 0.f);
                *(__half2*)&g_hh[(size_t)row1 * HID_DIM + col] = __floats2half2_rn(ox, oy);
                s0 += ox; q0 += ox * ox;
                s1 += oy; q1 += oy * oy;
            }
        }
        #pragma unroll
        for (int o = 4; o < 32; o <<= 1) {
            s0 += __shfl_xor_sync(0xffffffffu, s0, o);
            s1 += __shfl_xor_sync(0xffffffffu, s1, o);
            q0 += __shfl_xor_sync(0xffffffffu, q0, o);
            q1 += __shfl_xor_sync(0xffffffffu, q1, o);
        }
        if (lane < 4) {
            atomicAdd(&g_bnsum[col], s0);
            atomicAdd(&g_bnsum[col + 1], s1);
            atomicAdd(&g_bnsq[col], q0);
            atomicAdd(&g_bnsq[col + 1], q1);
        }
    }
}

// ---------------- BN finalize ----------------
__global__ void k_bnfin() {
    int c = blockIdx.x * blockDim.x + threadIdx.x;
    if (c < HID_DIM) {
        float m = g_bnsum[c] * (1.f / N_NODES);
        float var = g_bnsq[c] * (1.f / N_NODES) - m * m;
        if (var < 0.f) var = 0.f;
        g_mean[c] = m;
        g_rstd[c] = rsqrtf(var + BN_EPS);
    }
}

// projection: g[i] = (BN(hh[i]) * out_norm[i]) @ Wout  (2048 -> 3), fp16 h reads
__global__ __launch_bounds__(256) void k_proj(const float* __restrict__ Wout) {
    __shared__ float sW[HID_DIM * OUT_DIM];
    __shared__ float sMean[HID_DIM];
    __shared__ float sRstd[HID_DIM];
    int tid = threadIdx.x;
    for (int i = tid; i < HID_DIM * OUT_DIM; i += 256) sW[i] = Wout[i];
    for (int i = tid; i < HID_DIM; i += 256) { sMean[i] = g_mean[i]; sRstd[i] = g_rstd[i]; }
    __syncthreads();
    int warp = tid >> 5;
    int lane = tid & 31;
    int row = blockIdx.x * 8 + warp;
    if (row >= N_NODES) return;
    const __half* hr = &g_hh[(size_t)row * HID_DIM];
    float p0 = 0, p1 = 0, p2 = 0;
    #pragma unroll 4
    for (int i = 0; i < HID_DIM / 64; i++) {
        int c = lane * 2 + i * 64;
        float2 f = __half22float2(*(const __half2*)&hr[c]);
        float hn0 = (f.x - sMean[c]) * sRstd[c];
        float hn1 = (f.y - sMean[c + 1]) * sRstd[c + 1];
        p0 += hn0 * sW[c * 3 + 0] + hn1 * sW[c * 3 + 3];
        p1 += hn0 * sW[c * 3 + 1] + hn1 * sW[c * 3 + 4];
        p2 += hn0 * sW[c * 3 + 2] + hn1 * sW[c * 3 + 5];
    }
    #pragma unroll
    for (int o = 16; o > 0; o >>= 1) {
        p0 += __shfl_xor_sync(0xffffffffu, p0, o);
        p1 += __shfl_xor_sync(0xffffffffu, p1, o);
        p2 += __shfl_xor_sync(0xffffffffu, p2, o);
    }
    if (lane == 0) {
        float on = g_outnorm[row];
        g_g[row * 3 + 0] = p0 * on;
        g_g[row * 3 + 1] = p1 * on;
        g_g[row * 3 + 2] = p2 * on;
    }
}

// SpMM2 (dim 3) + softmax
__global__ __launch_bounds__(256) void k_spmm2(const float* __restrict__ bout,
                                               float* __restrict__ out) {
    int tid = threadIdx.x;
    int warp = tid >> 5;
    int lane = tid & 31;
    int row = blockIdx.x * 8 + warp;
    if (row >= N_NODES) return;
    int beg = g_off[row], end = g_off[row + 1];
    float a0 = 0, a1 = 0, a2 = 0;
    for (int j = beg + lane; j < end; j += 32) {
        int s = g_col[j];
        a0 += g_g[s * 3 + 0];
        a1 += g_g[s * 3 + 1];
        a2 += g_g[s * 3 + 2];
    }
    #pragma unroll
    for (int o = 16; o > 0; o >>= 1) {
        a0 += __shfl_xor_sync(0xffffffffu, a0, o);
        a1 += __shfl_xor_sync(0xffffffffu, a1, o);
        a2 += __shfl_xor_sync(0xffffffffu, a2, o);
    }
    if (lane == 0) {
        float inw = g_innorm[row];
        float v0 = a0 * inw + bout[0];
        float v1 = a1 * inw + bout[1];
        float v2 = a2 * inw + bout[2];
        float m = fmaxf(v0, fmaxf(v1, v2));
        float e0 = __expf(v0 - m), e1 = __expf(v1 - m), e2 = __expf(v2 - m);
        float inv = 1.f / (e0 + e1 + e2);
        out[row * 3 + 0] = e0 * inv;
        out[row * 3 + 1] = e1 * inv;
        out[row * 3 + 2] = e2 * inv;
    }
}

// ---------------- launch ----------------
extern "C" void kernel_launch(void* const* d_in, const int* in_sizes, int n_in,
                              void* d_out, int out_size) {
    const float* in_feat = (const float*)d_in[0];
    const int*   src     = (const int*)d_in[1];
    const int*   dst     = (const int*)d_in[2];
    const float* W1      = (const float*)d_in[3];
    const float* b1      = (const float*)d_in[4];
    const float* Wout    = (const float*)d_in[5];
    const float* bout    = (const float*)d_in[6];
    float* out = (float*)d_out;

    cudaFuncSetAttribute(k_gemm_mma, cudaFuncAttributeMaxDynamicSharedMemorySize, GDYN);

    k_zero<<<(N_NODES + 255) / 256, 256>>>();
    k_deg<<<(N_EDGES + 255) / 256, 256>>>(src, dst);
    k_norm<<<(N_NODES + 255) / 256, 256>>>();
    k_scan1<<<SCAN_BLOCKS, 256>>>();
    k_scan2<<<1, 256>>>();
    k_scan3<<<SCAN_BLOCKS, 256>>>();
    k_fill<<<(N_EDGES + 255) / 256, 256>>>(src, dst);
    k_transw<<<(IN_DIM * HID_DIM + 255) / 256, 256>>>(W1);
    k_prep<<<(N_NODES * (IN_DIM / 4) + 255) / 256, 256>>>(in_feat);
    k_spmm1<<<N_NODES, 256>>>();
    dim3 gg(HID_DIM / GBN, (N_NODES + GBM - 1) / GBM);
    k_gemm_mma<<<gg, 256, GDYN>>>(b1);
    k_bnfin<<<(HID_DIM + 255) / 256, 256>>>();
    k_proj<<<(N_NODES + 7) / 8, 256>>>(Wout);
    k_spmm2<<<(N_NODES + 7) / 8, 256>>>(bout, out);
}

// round 14
// speedup vs baseline: 2.6282x; 1.0630x over previous
#include <cuda_runtime.h>
#include <cuda_fp16.h>
#include <math.h>
#include <stdint.h>

#define N_NODES 50000
#define N_EDGES 1600000
#define IN_DIM  1024
#define HID_DIM 2048
#define OUT_DIM 3
#define BN_EPS  1e-5f
#define SCAN_BLOCKS ((N_NODES + 255) / 256)   // 196

// ---------------- scratch ----------------
__device__ int   g_outdeg[N_NODES];
__device__ int   g_indeg[N_NODES];
__device__ float g_outnorm[N_NODES];
__device__ float g_innorm[N_NODES];
__device__ int   g_off[N_NODES + 1];
__device__ int   g_pos[N_NODES];
__device__ int   g_blocksum[SCAN_BLOCKS];
__device__ int   g_col[N_EDGES];
__device__ __half g_Xh[(size_t)N_NODES * IN_DIM];   // 100 MB: fp16(out_norm * X)
__device__ __half g_Ah[(size_t)N_NODES * IN_DIM];   // 100 MB: fp16 aggregated A
__device__ __half g_Wt[(size_t)HID_DIM * IN_DIM];   // 4 MB  [N,K] fp16 W1^T
__device__ __half g_hh[(size_t)N_NODES * HID_DIM];  // 205 MB fp16 relu(h)
__device__ float g_bnsum[HID_DIM];
__device__ float g_bnsq[HID_DIM];
__device__ float g_mean[HID_DIM];
__device__ float g_rstd[HID_DIM];
__device__ float g_g[(size_t)N_NODES * OUT_DIM];

// ---------------- PTX helpers (sm_80-compatible only) ----------------
__device__ __forceinline__ uint32_t smem_u32(const void* p) {
    uint32_t a;
    asm("{ .reg .u64 t; cvta.to.shared.u64 t, %1; cvt.u32.u64 %0, t; }" : "=r"(a) : "l"(p));
    return a;
}
__device__ __forceinline__ void cp_async16(uint32_t dst, const void* src, int srcsize) {
    asm volatile("cp.async.cg.shared.global [%0], [%1], 16, %2;\n"
                 :: "r"(dst), "l"(src), "r"(srcsize));
}
#define CP_COMMIT() asm volatile("cp.async.commit_group;\n" ::: "memory")
template<int N> __device__ __forceinline__ void cp_wait() {
    asm volatile("cp.async.wait_group %0;\n" :: "n"(N) : "memory");
}
__device__ __forceinline__ void ldsm4(uint32_t* r, uint32_t addr) {
    asm volatile("ldmatrix.sync.aligned.m8n8.x4.shared.b16 {%0,%1,%2,%3}, [%4];"
                 : "=r"(r[0]), "=r"(r[1]), "=r"(r[2]), "=r"(r[3]) : "r"(addr));
}
__device__ __forceinline__ void mma16816(float* d, const uint32_t* a, uint32_t b0, uint32_t b1) {
    asm volatile(
        "mma.sync.aligned.m16n8k16.row.col.f32.f16.f16.f32 "
        "{%0,%1,%2,%3}, {%4,%5,%6,%7}, {%8,%9}, {%0,%1,%2,%3};"
        : "+f"(d[0]), "+f"(d[1]), "+f"(d[2]), "+f"(d[3])
        : "r"(a[0]), "r"(a[1]), "r"(a[2]), "r"(a[3]), "r"(b0), "r"(b1));
}

// ---------------- small kernels ----------------
__global__ void k_zero() {
    int i = blockIdx.x * blockDim.x + threadIdx.x;
    if (i < N_NODES) { g_outdeg[i] = 0; g_indeg[i] = 0; }
    if (i < HID_DIM) { g_bnsum[i] = 0.f; g_bnsq[i] = 0.f; }
}

__global__ void k_deg(const int* __restrict__ src, const int* __restrict__ dst) {
    int e = blockIdx.x * blockDim.x + threadIdx.x;
    if (e < N_EDGES) {
        atomicAdd(&g_outdeg[src[e]], 1);
        atomicAdd(&g_indeg[dst[e]], 1);
    }
}

__global__ void k_norm() {
    int i = blockIdx.x * blockDim.x + threadIdx.x;
    if (i < N_NODES) {
        int od = g_outdeg[i]; if (od < 1) od = 1;
        int id = g_indeg[i];  if (id < 1) id = 1;
        g_outnorm[i] = rsqrtf((float)od);
        g_innorm[i]  = rsqrtf((float)id);
    }
}

// multi-block exclusive scan of g_indeg -> g_off
__global__ void k_scan1() {
    __shared__ int sdata[256];
    int t = threadIdx.x;
    int i = blockIdx.x * 256 + t;
    int x = (i < N_NODES) ? g_indeg[i] : 0;
    sdata[t] = x;
    __syncthreads();
    #pragma unroll
    for (int ofs = 1; ofs < 256; ofs <<= 1) {
        int v = (t >= ofs) ? sdata[t - ofs] : 0;
        __syncthreads();
        sdata[t] += v;
        __syncthreads();
    }
    if (i < N_NODES) g_off[i] = sdata[t] - x;
    if (t == 255) g_blocksum[blockIdx.x] = sdata[255];
}

__global__ void k_scan2() {
    __shared__ int sdata[256];
    int t = threadIdx.x;
    int x = (t < SCAN_BLOCKS) ? g_blocksum[t] : 0;
    sdata[t] = x;
    __syncthreads();
    #pragma unroll
    for (int ofs = 1; ofs < 256; ofs <<= 1) {
        int v = (t >= ofs) ? sdata[t - ofs] : 0;
        __syncthreads();
        sdata[t] += v;
        __syncthreads();
    }
    if (t < SCAN_BLOCKS) g_blocksum[t] = sdata[t] - x;
}

__global__ void k_scan3() {
    int t = threadIdx.x;
    int i = blockIdx.x * 256 + t;
    if (i < N_NODES) {
        int v = g_off[i] + g_blocksum[blockIdx.x];
        g_off[i] = v;
        g_pos[i] = v;
    }
    if (i == 0) g_off[N_NODES] = N_EDGES;
}

__global__ void k_fill(const int* __restrict__ src, const int* __restrict__ dst) {
    int e = blockIdx.x * blockDim.x + threadIdx.x;
    if (e < N_EDGES) {
        int p = atomicAdd(&g_pos[dst[e]], 1);
        g_col[p] = src[e];
    }
}

// transpose W1 [K,N] -> Wt [N,K] fp16
__global__ void k_transw(const float* __restrict__ W1) {
    int idx = blockIdx.x * blockDim.x + threadIdx.x;
    if (idx < IN_DIM * HID_DIM) {
        int k = idx / HID_DIM, n = idx % HID_DIM;
        g_Wt[(size_t)n * IN_DIM + k] = __float2half_rn(W1[idx]);
    }
}

// pre-scale + quantize: Xh[i] = fp16(out_norm[i] * X[i])
__global__ void k_prep(const float* __restrict__ X) {
    int idx = blockIdx.x * blockDim.x + threadIdx.x;   // one float4 / thread
    if (idx < N_NODES * (IN_DIM / 4)) {
        int row = idx >> 8;                            // IN_DIM/4 = 256
        float w = g_outnorm[row];
        float4 v = *(const float4*)&X[(size_t)idx * 4];
        __half2* d = (__half2*)&g_Xh[(size_t)idx * 4];
        d[0] = __floats2half2_rn(v.x * w, v.y * w);
        d[1] = __floats2half2_rn(v.z * w, v.w * w);
    }
}

// SpMM1: Ah[row] = fp16( in_norm[row] * sum Xh[s] )
// 128 threads; each thread owns 8 halves (16B); 2-edge unroll for MLP.
__global__ void __launch_bounds__(128) k_spmm1() {
    int row = blockIdx.x;
    int t = threadIdx.x;               // 0..127
    int beg = g_off[row], end = g_off[row + 1];
    size_t coff = (size_t)t * 8;
    float a0 = 0.f, a1 = 0.f, a2 = 0.f, a3 = 0.f;
    float a4 = 0.f, a5 = 0.f, a6 = 0.f, a7 = 0.f;
    int j = beg;
    for (; j + 1 < end; j += 2) {
        int s0 = g_col[j];
        int s1 = g_col[j + 1];
        uint4 u0 = *(const uint4*)&g_Xh[(size_t)s0 * IN_DIM + coff];
        uint4 u1 = *(const uint4*)&g_Xh[(size_t)s1 * IN_DIM + coff];
        float2 f;
        f = __half22float2(*(__half2*)&u0.x); a0 += f.x; a1 += f.y;
        f = __half22float2(*(__half2*)&u0.y); a2 += f.x; a3 += f.y;
        f = __half22float2(*(__half2*)&u0.z); a4 += f.x; a5 += f.y;
        f = __half22float2(*(__half2*)&u0.w); a6 += f.x; a7 += f.y;
        f = __half22float2(*(__half2*)&u1.x); a0 += f.x; a1 += f.y;
        f = __half22float2(*(__half2*)&u1.y); a2 += f.x; a3 += f.y;
        f = __half22float2(*(__half2*)&u1.z); a4 += f.x; a5 += f.y;
        f = __half22float2(*(__half2*)&u1.w); a6 += f.x; a7 += f.y;
    }
    if (j < end) {
        int s0 = g_col[j];
        uint4 u0 = *(const uint4*)&g_Xh[(size_t)s0 * IN_DIM + coff];
        float2 f;
        f = __half22float2(*(__half2*)&u0.x); a0 += f.x; a1 += f.y;
        f = __half22float2(*(__half2*)&u0.y); a2 += f.x; a3 += f.y;
        f = __half22float2(*(__half2*)&u0.z); a4 += f.x; a5 += f.y;
        f = __half22float2(*(__half2*)&u0.w); a6 += f.x; a7 += f.y;
    }
    float inw = g_innorm[row];
    uint4 o;
    __half2 h;
    h = __floats2half2_rn(a0 * inw, a1 * inw); o.x = *(uint32_t*)&h;
    h = __floats2half2_rn(a2 * inw, a3 * inw); o.y = *(uint32_t*)&h;
    h = __floats2half2_rn(a4 * inw, a5 * inw); o.z = *(uint32_t*)&h;
    h = __floats2half2_rn(a6 * inw, a7 * inw); o.w = *(uint32_t*)&h;
    *(uint4*)&g_Ah[(size_t)row * IN_DIM + coff] = o;
}

// ---------------- mma.sync GEMM1, single-term fp16 ----------------
// BM=128, BN=128, BK=64; 3-stage cp.async pipeline; 8 warps 4m x 2n; warp tile 32x64
#define GBM 128
#define GBN 128
#define STAGE_B 32768           // A 16KB + B 16KB
#define N_ITERS 16              // 16 K-chunks of 64
#define GDYN (3 * STAGE_B)

__device__ __forceinline__ void g_load_stage(uint32_t sbase, int m0, int n0, int k0, int tid) {
    #pragma unroll
    for (int i = 0; i < 4; i++) {            // A: 128 rows x 64 fp16
        int cid = tid + i * 256;
        int r = cid >> 3, c = cid & 7;
        int gm = m0 + r;
        int ok = (gm < N_NODES);
        const char* src = (const char*)(g_Ah + (size_t)(ok ? gm : 0) * IN_DIM + k0) + c * 16;
        uint32_t dst = sbase + r * 128 + ((c ^ (r & 7)) * 16);
        cp_async16(dst, src, ok ? 16 : 0);
    }
    #pragma unroll
    for (int i = 0; i < 4; i++) {            // B: 128 n-rows x 64 fp16
        int cid = tid + i * 256;
        int r = cid >> 3, c = cid & 7;
        const char* src = (const char*)(g_Wt + (size_t)(n0 + r) * IN_DIM + k0) + c * 16;
        uint32_t dst = sbase + 16384 + r * 128 + ((c ^ (r & 7)) * 16);
        cp_async16(dst, src, 16);
    }
}

__global__ void __launch_bounds__(256, 2) k_gemm_mma(const float* __restrict__ bias) {
    extern __shared__ char smem[];
    uint32_t sb = smem_u32(smem);
    int tid = threadIdx.x;
    int wid = tid >> 5;
    int lane = tid & 31;
    int n0 = blockIdx.x * GBN;
    int m0 = blockIdx.y * GBM;
    int wm = (wid >> 1) * 32;
    int wn = (wid & 1) * 64;

    float acc[2][8][4];
    #pragma unroll
    for (int i = 0; i < 2; i++)
        #pragma unroll
        for (int j = 0; j < 8; j++)
            #pragma unroll
            for (int q = 0; q < 4; q++) acc[i][j][q] = 0.f;

    g_load_stage(sb + 0 * STAGE_B, m0, n0, 0, tid);
    CP_COMMIT();
    g_load_stage(sb + 1 * STAGE_B, m0, n0, 64, tid);
    CP_COMMIT();

    for (int it = 0; it < N_ITERS; it++) {
        cp_wait<1>();
        __syncthreads();
        int nx = it + 2;
        if (nx < N_ITERS)
            g_load_stage(sb + (nx % 3) * STAGE_B, m0, n0, nx * 64, tid);
        CP_COMMIT();

        uint32_t bufA = sb + (it % 3) * STAGE_B;
        uint32_t bufB = bufA + 16384;
        #pragma unroll
        for (int ks = 0; ks < 4; ks++) {
            uint32_t a[2][4], b[4][4];
            #pragma unroll
            for (int am = 0; am < 2; am++) {
                int r = wm + am * 16 + (lane & 15);
                int ch = ks * 2 + (lane >> 4);
                ldsm4(a[am], bufA + r * 128 + ((ch ^ (r & 7)) * 16));
            }
            #pragma unroll
            for (int bp = 0; bp < 4; bp++) {
                int r = wn + bp * 16 + (lane & 15);
                int ch = ks * 2 + (lane >> 4);
                ldsm4(b[bp], bufB + r * 128 + ((ch ^ (r & 7)) * 16));
            }
            #pragma unroll
            for (int am = 0; am < 2; am++)
                #pragma unroll
                for (int bp = 0; bp < 4; bp++) {
                    mma16816(acc[am][bp * 2 + 0], a[am], b[bp][0], b[bp][2]);
                    mma16816(acc[am][bp * 2 + 1], a[am], b[bp][1], b[bp][3]);
                }
        }
        __syncthreads();
    }

    // epilogue: +bias, relu, fp16 store, fused BN partial sums (from fp32 values)
    #pragma unroll
    for (int bn8 = 0; bn8 < 8; bn8++) {
        int col = n0 + wn + bn8 * 8 + (lane & 3) * 2;
        float bv0 = __ldg(&bias[col]);
        float bv1 = __ldg(&bias[col + 1]);
        float s0 = 0.f, s1 = 0.f, q0 = 0.f, q1 = 0.f;
        #pragma unroll
        for (int am = 0; am < 2; am++) {
            int row0 = m0 + wm + am * 16 + (lane >> 2);
            if (row0 < N_NODES) {
                float ox = fmaxf(acc[am][bn8][0] + bv0, 0.f);
                float oy = fmaxf(acc[am][bn8][1] + bv1, 0.f);
                *(__half2*)&g_hh[(size_t)row0 * HID_DIM + col] = __floats2half2_rn(ox, oy);
                s0 += ox; q0 += ox * ox;
                s1 += oy; q1 += oy * oy;
            }
            int row1 = row0 + 8;
            if (row1 < N_NODES) {
                float ox = fmaxf(acc[am][bn8][2] + bv0, 0.f);
                float oy = fmaxf(acc[am][bn8][3] + bv1, 0.f);
                *(__half2*)&g_hh[(size_t)row1 * HID_DIM + col] = __floats2half2_rn(ox, oy);
                s0 += ox; q0 += ox * ox;
                s1 += oy; q1 += oy * oy;
            }
        }
        #pragma unroll
        for (int o = 4; o < 32; o <<= 1) {
            s0 += __shfl_xor_sync(0xffffffffu, s0, o);
            s1 += __shfl_xor_sync(0xffffffffu, s1, o);
            q0 += __shfl_xor_sync(0xffffffffu, q0, o);
            q1 += __shfl_xor_sync(0xffffffffu, q1, o);
        }
        if (lane < 4) {
            atomicAdd(&g_bnsum[col], s0);
            atomicAdd(&g_bnsum[col + 1], s1);
            atomicAdd(&g_bnsq[col], q0);
            atomicAdd(&g_bnsq[col + 1], q1);
        }
    }
}

// ---------------- BN finalize ----------------
__global__ void k_bnfin() {
    int c = blockIdx.x * blockDim.x + threadIdx.x;
    if (c < HID_DIM) {
        float m = g_bnsum[c] * (1.f / N_NODES);
        float var = g_bnsq[c] * (1.f / N_NODES) - m * m;
        if (var < 0.f) var = 0.f;
        g_mean[c] = m;
        g_rstd[c] = rsqrtf(var + BN_EPS);
    }
}

// projection: g[i] = (BN(hh[i]) * out_norm[i]) @ Wout  (2048 -> 3), fp16 h reads
__global__ __launch_bounds__(256) void k_proj(const float* __restrict__ Wout) {
    __shared__ float sW[HID_DIM * OUT_DIM];
    __shared__ float sMean[HID_DIM];
    __shared__ float sRstd[HID_DIM];
    int tid = threadIdx.x;
    for (int i = tid; i < HID_DIM * OUT_DIM; i += 256) sW[i] = Wout[i];
    for (int i = tid; i < HID_DIM; i += 256) { sMean[i] = g_mean[i]; sRstd[i] = g_rstd[i]; }
    __syncthreads();
    int warp = tid >> 5;
    int lane = tid & 31;
    int row = blockIdx.x * 8 + warp;
    if (row >= N_NODES) return;
    const __half* hr = &g_hh[(size_t)row * HID_DIM];
    float p0 = 0, p1 = 0, p2 = 0;
    #pragma unroll 4
    for (int i = 0; i < HID_DIM / 64; i++) {
        int c = lane * 2 + i * 64;
        float2 f = __half22float2(*(const __half2*)&hr[c]);
        float hn0 = (f.x - sMean[c]) * sRstd[c];
        float hn1 = (f.y - sMean[c + 1]) * sRstd[c + 1];
        p0 += hn0 * sW[c * 3 + 0] + hn1 * sW[c * 3 + 3];
        p1 += hn0 * sW[c * 3 + 1] + hn1 * sW[c * 3 + 4];
        p2 += hn0 * sW[c * 3 + 2] + hn1 * sW[c * 3 + 5];
    }
    #pragma unroll
    for (int o = 16; o > 0; o >>= 1) {
        p0 += __shfl_xor_sync(0xffffffffu, p0, o);
        p1 += __shfl_xor_sync(0xffffffffu, p1, o);
        p2 += __shfl_xor_sync(0xffffffffu, p2, o);
    }
    if (lane == 0) {
        float on = g_outnorm[row];
        g_g[row * 3 + 0] = p0 * on;
        g_g[row * 3 + 1] = p1 * on;
        g_g[row * 3 + 2] = p2 * on;
    }
}

// SpMM2 (dim 3) + softmax
__global__ __launch_bounds__(256) void k_spmm2(const float* __restrict__ bout,
                                               float* __restrict__ out) {
    int tid = threadIdx.x;
    int warp = tid >> 5;
    int lane = tid & 31;
    int row = blockIdx.x * 8 + warp;
    if (row >= N_NODES) return;
    int beg = g_off[row], end = g_off[row + 1];
    float a0 = 0, a1 = 0, a2 = 0;
    for (int j = beg + lane; j < end; j += 32) {
        int s = g_col[j];
        a0 += g_g[s * 3 + 0];
        a1 += g_g[s * 3 + 1];
        a2 += g_g[s * 3 + 2];
    }
    #pragma unroll
    for (int o = 16; o > 0; o >>= 1) {
        a0 += __shfl_xor_sync(0xffffffffu, a0, o);
        a1 += __shfl_xor_sync(0xffffffffu, a1, o);
        a2 += __shfl_xor_sync(0xffffffffu, a2, o);
    }
    if (lane == 0) {
        float inw = g_innorm[row];
        float v0 = a0 * inw + bout[0];
        float v1 = a1 * inw + bout[1];
        float v2 = a2 * inw + bout[2];
        float m = fmaxf(v0, fmaxf(v1, v2));
        float e0 = __expf(v0 - m), e1 = __expf(v1 - m), e2 = __expf(v2 - m);
        float inv = 1.f / (e0 + e1 + e2);
        out[row * 3 + 0] = e0 * inv;
        out[row * 3 + 1] = e1 * inv;
        out[row * 3 + 2] = e2 * inv;
    }
}

// ---------------- launch ----------------
extern "C" void kernel_launch(void* const* d_in, const int* in_sizes, int n_in,
                              void* d_out, int out_size) {
    const float* in_feat = (const float*)d_in[0];
    const int*   src     = (const int*)d_in[1];
    const int*   dst     = (const int*)d_in[2];
    const float* W1      = (const float*)d_in[3];
    const float* b1      = (const float*)d_in[4];
    const float* Wout    = (const float*)d_in[5];
    const float* bout    = (const float*)d_in[6];
    float* out = (float*)d_out;

    cudaFuncSetAttribute(k_gemm_mma, cudaFuncAttributeMaxDynamicSharedMemorySize, GDYN);

    k_zero<<<(N_NODES + 255) / 256, 256>>>();
    k_deg<<<(N_EDGES + 255) / 256, 256>>>(src, dst);
    k_norm<<<(N_NODES + 255) / 256, 256>>>();
    k_scan1<<<SCAN_BLOCKS, 256>>>();
    k_scan2<<<1, 256>>>();
    k_scan3<<<SCAN_BLOCKS, 256>>>();
    k_fill<<<(N_EDGES + 255) / 256, 256>>>(src, dst);
    k_transw<<<(IN_DIM * HID_DIM + 255) / 256, 256>>>(W1);
    k_prep<<<(N_NODES * (IN_DIM / 4) + 255) / 256, 256>>>(in_feat);
    k_spmm1<<<N_NODES, 128>>>();
    dim3 gg(HID_DIM / GBN, (N_NODES + GBM - 1) / GBM);
    k_gemm_mma<<<gg, 256, GDYN>>>(b1);
    k_bnfin<<<(HID_DIM + 255) / 256, 256>>>();
    k_proj<<<(N_NODES + 7) / 8, 256>>>(Wout);
    k_spmm2<<<(N_NODES + 7) / 8, 256>>>(bout, out);
}